// round 13
// baseline (speedup 1.0000x reference)
#include <cuda_runtime.h>
#include <math.h>
#include <stdint.h>

#define BB 4
#define TT 1024
#define EE 1024
#define HH 16
#define FFDIM 64
#define LN_N ((size_t)TT * EE)

// ---------------- scratch (static device globals; no allocation) -------------
__device__ float g_wq[EE * EE];
__device__ float g_wk[EE * EE];
__device__ float g_q[BB * TT * EE];
__device__ float g_k[BB * TT * EE];
__device__ float g_v[BB * TT * EE];
__device__ float g_zf[BB * TT * EE];
__device__ float g_z1[BB * TT * EE];
__device__ float g_z2[BB * TT * EE];
__device__ double g_part[BB * 64 * 2];
__device__ float g_stats[BB * 2];
__device__ uint32_t g_wvhi[EE * EE];
__device__ uint32_t g_wffhi[EE * EE];
__device__ uint32_t g_frhi[BB * EE * EE];
__device__ uint32_t g_athi[BB * TT * EE];  // transposed activation [K][M]

// ---------------- helpers ----------------------------------------------------
__device__ __forceinline__ uint32_t f2tf(float x) {
    uint32_t r;
    asm("cvt.rna.tf32.f32 %0, %1;" : "=r"(r) : "f"(x));
    return r;
}

__device__ __forceinline__ void mma8(float c[4], const uint32_t a[4], const uint32_t b[2]) {
    asm volatile(
        "mma.sync.aligned.m16n8k8.row.col.f32.tf32.tf32.f32 "
        "{%0,%1,%2,%3}, {%4,%5,%6,%7}, {%8,%9}, {%0,%1,%2,%3};\n"
        : "+f"(c[0]), "+f"(c[1]), "+f"(c[2]), "+f"(c[3])
        : "r"(a[0]), "r"(a[1]), "r"(a[2]), "r"(a[3]), "r"(b[0]), "r"(b[1]));
}

__device__ __forceinline__ uint32_t smem_u32(const void* p) {
    return (uint32_t)__cvta_generic_to_shared(p);
}
__device__ __forceinline__ void cpasync16(uint32_t dst, const void* src) {
    asm volatile("cp.async.ca.shared.global [%0], [%1], 16;\n" ::"r"(dst), "l"(src));
}

// ---------------- merged weight repacks (one launch) -------------------------
__global__ void repack_all(const float* __restrict__ qw,
                           const float* __restrict__ kw,
                           const float* __restrict__ vw,
                           const float* __restrict__ ffw,
                           const float* __restrict__ frw) {
    int idx = blockIdx.x * blockDim.x + threadIdx.x;
    if (idx < EE * EE) {
        int e = idx / EE, n = idx % EE;
        int h = n >> 6, f = n & 63;
        int src = h * (EE * FFDIM) + e * FFDIM + f;
        g_wq[idx] = qw[src];
        g_wk[idx] = kw[src];
        g_wvhi[idx] = f2tf(vw[src]);
        g_wffhi[idx] = f2tf(ffw[n * EE + e]);
    }
    int idx2 = idx - EE * EE;
    if (idx2 >= 0 && idx2 < BB * EE * EE) g_frhi[idx2] = f2tf(frw[idx2]);
}

// ---------------- tiled transpose + tf32: [nb][M][K] -> [nb][K][M] -----------
__global__ __launch_bounds__(256) void transpose_tf(
    const float* __restrict__ in, uint32_t* __restrict__ ohi, int M, int K) {
    __shared__ float t[32][33];
    size_t bo = (size_t)blockIdx.z * M * K;
    in += bo; ohi += bo;
    int m0 = blockIdx.y * 32, k0 = blockIdx.x * 32;
    int tx = threadIdx.x & 31, ty = threadIdx.x >> 5;
#pragma unroll
    for (int i = ty; i < 32; i += 8) t[i][tx] = in[(size_t)(m0 + i) * K + k0 + tx];
    __syncthreads();
#pragma unroll
    for (int i = ty; i < 32; i += 8) {
        ohi[(size_t)(k0 + i) * M + m0 + tx] = f2tf(t[tx][i]);
    }
}

// ---------------- merged QKV GEMM (FROZEN fp32 chain for Q,K) ----------------
#define T1_STAGE_U32 (2 * 16 * 136)
__global__ __launch_bounds__(256, 2) void gemm_qkv(
    const float* __restrict__ A, const float* __restrict__ B0,
    const float* __restrict__ B1, float* __restrict__ C0, float* __restrict__ C1,
    const uint32_t* __restrict__ Ahi, const uint32_t* __restrict__ Bhi,
    float* __restrict__ CV, int M, int N, int K) {
    extern __shared__ uint32_t smp[];
    int m0 = blockIdx.y * 128, n0 = blockIdx.x * 128;
    int tid = threadIdx.x;

    if (blockIdx.z < 2) {
        const float* Bm = blockIdx.z ? B1 : B0;
        float* C = blockIdx.z ? C1 : C0;
        float* Asf = (float*)smp;
        float* Bsf = Asf + 2 * 16 * 132;
        int ty = tid >> 4, tx = tid & 15;
        float acc[8][8] = {};
        int ar = tid >> 2;
        int ac4 = (tid & 3) * 4;
        int bk = tid >> 5;
        int bc4 = (tid & 31) * 4;

        uint32_t bd0[2], bd1[2];
        bd0[0] = smem_u32(&Bsf[0 * 2048 + bk * 128 + bc4]);
        bd0[1] = smem_u32(&Bsf[1 * 2048 + bk * 128 + bc4]);
        bd1[0] = smem_u32(&Bsf[0 * 2048 + (bk + 8) * 128 + bc4]);
        bd1[1] = smem_u32(&Bsf[1 * 2048 + (bk + 8) * 128 + bc4]);

        cpasync16(bd0[0], &Bm[(size_t)bk * N + n0 + bc4]);
        cpasync16(bd1[0], &Bm[(size_t)(bk + 8) * N + n0 + bc4]);
        asm volatile("cp.async.commit_group;\n");
        float4 ra0 = *(const float4*)&A[(size_t)(m0 + ar) * K + ac4];
        float4 ra1 = *(const float4*)&A[(size_t)(m0 + ar + 64) * K + ac4];
        Asf[(ac4 + 0) * 132 + ar] = ra0.x; Asf[(ac4 + 1) * 132 + ar] = ra0.y;
        Asf[(ac4 + 2) * 132 + ar] = ra0.z; Asf[(ac4 + 3) * 132 + ar] = ra0.w;
        Asf[(ac4 + 0) * 132 + ar + 64] = ra1.x; Asf[(ac4 + 1) * 132 + ar + 64] = ra1.y;
        Asf[(ac4 + 2) * 132 + ar + 64] = ra1.z; Asf[(ac4 + 3) * 132 + ar + 64] = ra1.w;
        asm volatile("cp.async.wait_group 0;\n");
        __syncthreads();

        int nt = K / 16;
        for (int t = 0; t < nt; t++) {
            int s = t & 1;
            if (t + 1 < nt) {
                int k0 = (t + 1) * 16;
                cpasync16(bd0[s ^ 1], &Bm[(size_t)(k0 + bk) * N + n0 + bc4]);
                cpasync16(bd1[s ^ 1], &Bm[(size_t)(k0 + bk + 8) * N + n0 + bc4]);
                asm volatile("cp.async.commit_group;\n");
                ra0 = *(const float4*)&A[(size_t)(m0 + ar) * K + k0 + ac4];
                ra1 = *(const float4*)&A[(size_t)(m0 + ar + 64) * K + k0 + ac4];
            }
            const float* Asc = Asf + s * 2112;
            const float* Bsc = Bsf + s * 2048;
#pragma unroll
            for (int k = 0; k < 16; k++) {
                float a[8], b[8];
                *(float4*)&a[0] = *(const float4*)&Asc[k * 132 + ty * 8];
                *(float4*)&a[4] = *(const float4*)&Asc[k * 132 + ty * 8 + 4];
                *(float4*)&b[0] = *(const float4*)&Bsc[k * 128 + tx * 8];
                *(float4*)&b[4] = *(const float4*)&Bsc[k * 128 + tx * 8 + 4];
#pragma unroll
                for (int i = 0; i < 8; i++)
#pragma unroll
                    for (int j = 0; j < 8; j++) acc[i][j] += a[i] * b[j];
            }
            if (t + 1 < nt) {
                int s2 = s ^ 1;
                float* Asn = Asf + s2 * 2112;
                Asn[(ac4 + 0) * 132 + ar] = ra0.x; Asn[(ac4 + 1) * 132 + ar] = ra0.y;
                Asn[(ac4 + 2) * 132 + ar] = ra0.z; Asn[(ac4 + 3) * 132 + ar] = ra0.w;
                Asn[(ac4 + 0) * 132 + ar + 64] = ra1.x; Asn[(ac4 + 1) * 132 + ar + 64] = ra1.y;
                Asn[(ac4 + 2) * 132 + ar + 64] = ra1.z; Asn[(ac4 + 3) * 132 + ar + 64] = ra1.w;
                asm volatile("cp.async.wait_group 0;\n");
            }
            __syncthreads();
        }
#pragma unroll
        for (int i = 0; i < 8; i++) {
            int m = m0 + ty * 8 + i;
            *(float4*)&C[(size_t)m * N + n0 + tx * 8] = *(float4*)&acc[i][0];
            *(float4*)&C[(size_t)m * N + n0 + tx * 8 + 4] = *(float4*)&acc[i][4];
        }
    } else {
        // 1xTF32 tensor path (V projection)
        int lane = tid & 31, w = tid >> 5;
        int wm = w & 1, wn = w >> 1;
        int g = lane >> 2, tig = lane & 3;
        float acc[4][4][4] = {};
        int crow = tid >> 4;
        int col0 = (tid & 15) * 4;
        uint32_t sbase = smem_u32(smp);
        const uint32_t STAGE_B = T1_STAGE_U32 * 4;
        uint32_t offA = ((0 * 16 + crow) * 136 + col0) * 4;
        uint32_t offB = ((1 * 16 + crow) * 136 + col0) * 4;

        int nt = K / 16;
#pragma unroll
        for (int p = 0; p < 2; p++) {
            uint32_t dst = sbase + p * STAGE_B;
            const uint32_t* ga = &Ahi[(size_t)(p * 16 + crow) * M + m0 + col0];
            const uint32_t* gb = &Bhi[(size_t)(p * 16 + crow) * N + n0 + col0];
            cpasync16(dst + offA, ga);
            cpasync16(dst + offA + 256, ga + 64);
            cpasync16(dst + offB, gb);
            cpasync16(dst + offB + 256, gb + 64);
            asm volatile("cp.async.commit_group;\n");
        }
        asm volatile("cp.async.wait_group 1;\n");
        __syncthreads();

        int sl = 2, sc = 0;
        for (int t = 0; t < nt; t++) {
            if (t + 2 < nt) {
                uint32_t dst = sbase + sl * STAGE_B;
                const uint32_t* ga = &Ahi[(size_t)((t + 2) * 16 + crow) * M + m0 + col0];
                const uint32_t* gb = &Bhi[(size_t)((t + 2) * 16 + crow) * N + n0 + col0];
                cpasync16(dst + offA, ga);
                cpasync16(dst + offA + 256, ga + 64);
                cpasync16(dst + offB, gb);
                cpasync16(dst + offB + 256, gb + 64);
            }
            asm volatile("cp.async.commit_group;\n");
            const uint32_t* As = smp + sc * T1_STAGE_U32;
            const uint32_t* Bs = As + 16 * 136;
#pragma unroll
            for (int kk = 0; kk < 16; kk += 8) {
                uint32_t af[4][4];
#pragma unroll
                for (int mi = 0; mi < 4; mi++) {
                    int mb = wm * 64 + mi * 16 + g;
                    af[mi][0] = As[(kk + tig) * 136 + mb];
                    af[mi][1] = As[(kk + tig) * 136 + mb + 8];
                    af[mi][2] = As[(kk + tig + 4) * 136 + mb];
                    af[mi][3] = As[(kk + tig + 4) * 136 + mb + 8];
                }
#pragma unroll
                for (int ni = 0; ni < 4; ni++) {
                    int nb = wn * 32 + ni * 8 + g;
                    uint32_t bf[2];
                    bf[0] = Bs[(kk + tig) * 136 + nb];
                    bf[1] = Bs[(kk + tig + 4) * 136 + nb];
#pragma unroll
                    for (int mi = 0; mi < 4; mi++) mma8(acc[mi][ni], af[mi], bf);
                }
            }
            asm volatile("cp.async.wait_group 1;\n");
            __syncthreads();
            sl = (sl == 2) ? 0 : sl + 1;
            sc = (sc == 2) ? 0 : sc + 1;
        }
#pragma unroll
        for (int mi = 0; mi < 4; mi++) {
            int m = m0 + wm * 64 + mi * 16 + g;
#pragma unroll
            for (int ni = 0; ni < 4; ni++) {
                int n = n0 + wn * 32 + ni * 8 + tig * 2;
                *(float2*)&CV[(size_t)m * N + n] =
                    make_float2(acc[mi][ni][0], acc[mi][ni][1]);
                *(float2*)&CV[(size_t)(m + 8) * N + n] =
                    make_float2(acc[mi][ni][2], acc[mi][ni][3]);
            }
        }
    }
}

// ---------------- 1xTF32 tensor-core GEMM, 3-stage cp.async pipeline ---------
template <bool RELU>
__global__ __launch_bounds__(256, 2) void gemm_tf1(
    const uint32_t* __restrict__ Ahi, const uint32_t* __restrict__ Bhi,
    float* __restrict__ C, int M, int N, int K,
    long sA, long sB, long sC, const float* __restrict__ bias) {
    extern __shared__ uint32_t smp[];
    Ahi += (size_t)blockIdx.z * sA;
    Bhi += (size_t)blockIdx.z * sB;
    C += (size_t)blockIdx.z * sC;
    int m0 = blockIdx.y * 128, n0 = blockIdx.x * 128;
    int tid = threadIdx.x, lane = tid & 31, w = tid >> 5;
    int wm = w & 1, wn = w >> 1;
    int g = lane >> 2, tig = lane & 3;
    float acc[4][4][4] = {};

    int crow = tid >> 4;
    int col0 = (tid & 15) * 4;
    uint32_t sbase = smem_u32(smp);
    const uint32_t STAGE_B = T1_STAGE_U32 * 4;
    uint32_t offA = ((0 * 16 + crow) * 136 + col0) * 4;
    uint32_t offB = ((1 * 16 + crow) * 136 + col0) * 4;

    int nt = K / 16;
#pragma unroll
    for (int p = 0; p < 2; p++) {
        uint32_t dst = sbase + p * STAGE_B;
        const uint32_t* ga = &Ahi[(size_t)(p * 16 + crow) * M + m0 + col0];
        const uint32_t* gb = &Bhi[(size_t)(p * 16 + crow) * N + n0 + col0];
        cpasync16(dst + offA, ga);
        cpasync16(dst + offA + 256, ga + 64);
        cpasync16(dst + offB, gb);
        cpasync16(dst + offB + 256, gb + 64);
        asm volatile("cp.async.commit_group;\n");
    }
    asm volatile("cp.async.wait_group 1;\n");
    __syncthreads();

    int sl = 2, sc = 0;
    for (int t = 0; t < nt; t++) {
        if (t + 2 < nt) {
            uint32_t dst = sbase + sl * STAGE_B;
            const uint32_t* ga = &Ahi[(size_t)((t + 2) * 16 + crow) * M + m0 + col0];
            const uint32_t* gb = &Bhi[(size_t)((t + 2) * 16 + crow) * N + n0 + col0];
            cpasync16(dst + offA, ga);
            cpasync16(dst + offA + 256, ga + 64);
            cpasync16(dst + offB, gb);
            cpasync16(dst + offB + 256, gb + 64);
        }
        asm volatile("cp.async.commit_group;\n");
        const uint32_t* As = smp + sc * T1_STAGE_U32;
        const uint32_t* Bs = As + 16 * 136;
#pragma unroll
        for (int kk = 0; kk < 16; kk += 8) {
            uint32_t af[4][4];
#pragma unroll
            for (int mi = 0; mi < 4; mi++) {
                int mb = wm * 64 + mi * 16 + g;
                af[mi][0] = As[(kk + tig) * 136 + mb];
                af[mi][1] = As[(kk + tig) * 136 + mb + 8];
                af[mi][2] = As[(kk + tig + 4) * 136 + mb];
                af[mi][3] = As[(kk + tig + 4) * 136 + mb + 8];
            }
#pragma unroll
            for (int ni = 0; ni < 4; ni++) {
                int nb = wn * 32 + ni * 8 + g;
                uint32_t bf[2];
                bf[0] = Bs[(kk + tig) * 136 + nb];
                bf[1] = Bs[(kk + tig + 4) * 136 + nb];
#pragma unroll
                for (int mi = 0; mi < 4; mi++) mma8(acc[mi][ni], af[mi], bf);
            }
        }
        asm volatile("cp.async.wait_group 1;\n");
        __syncthreads();
        sl = (sl == 2) ? 0 : sl + 1;
        sc = (sc == 2) ? 0 : sc + 1;
    }
#pragma unroll
    for (int mi = 0; mi < 4; mi++) {
        int m = m0 + wm * 64 + mi * 16 + g;
#pragma unroll
        for (int ni = 0; ni < 4; ni++) {
            int n = n0 + wn * 32 + ni * 8 + tig * 2;
            float b0 = bias ? bias[n] : 0.0f;
            float b1 = bias ? bias[n + 1] : 0.0f;
            float v0 = acc[mi][ni][0] + b0, v1 = acc[mi][ni][1] + b1;
            float v2 = acc[mi][ni][2] + b0, v3 = acc[mi][ni][3] + b1;
            if (RELU) {
                v0 = fmaxf(v0, 0.0f); v1 = fmaxf(v1, 0.0f);
                v2 = fmaxf(v2, 0.0f); v3 = fmaxf(v3, 0.0f);
            }
            *(float2*)&C[(size_t)m * N + n] = make_float2(v0, v1);
            *(float2*)&C[(size_t)(m + 8) * N + n] = make_float2(v2, v3);
        }
    }
}

// ---------------- fused attention, BQ=64 BK=64, 3 blocks/SM ------------------
// Scores: ascending-f fp32 fma + identical mask (FROZEN chain). ks aliases the
// full Ps buffer. PV is 1xTF32 (V hi only). Epilogue writes transposed tf32
// athi directly (bit-identical to the old zm->transpose_tf path).
struct __align__(16) AttnSmem {
    float qs[64][68];       // [f][q]   17408 B
    uint32_t Ps[64][68];    // [q][k], aliases ks [f][k]  17408 B
    uint32_t vhi[64][72];   // [k][f] tf32                18432 B
    float sm_m[64];
    float sm_l[64];
    float sm_sc[64];        //                              768 B
};                          // total 54016 B -> 3 blocks/SM

__global__ __launch_bounds__(256, 3) void attn_fused() {
    extern __shared__ char smraw[];
    AttnSmem* S = (AttnSmem*)smraw;
    float(*ks)[68] = (float(*)[68])S->Ps;
    int bh = blockIdx.y;
    int b = bh / HH, h = bh % HH;
    int q0 = blockIdx.x * 64;
    const float* qp = g_q + (size_t)b * TT * EE + h * FFDIM;
    const float* kp = g_k + (size_t)b * TT * EE + h * FFDIM;
    const float* vp = g_v + (size_t)b * TT * EE + h * FFDIM;

    int tid = threadIdx.x;
    int ty = tid >> 4, tx = tid & 15;
    int lane = tid & 31, w = tid >> 5;
    int wm = w >> 1, wn = w & 1;
    int g = lane >> 2, tig = lane & 3;
    int ar = tid >> 2;            // 0..63
    int ac4 = (tid & 3) * 4;

    // load Q tile once: 64 q-rows x 64 f -> qs[f][q]
#pragma unroll
    for (int c0 = 0; c0 < 64; c0 += 16) {
        const float4 va = *(const float4*)&qp[(size_t)(q0 + ar) * EE + c0 + ac4];
        S->qs[c0 + ac4 + 0][ar] = va.x;
        S->qs[c0 + ac4 + 1][ar] = va.y;
        S->qs[c0 + ac4 + 2][ar] = va.z;
        S->qs[c0 + ac4 + 3][ar] = va.w;
    }
    if (tid < 64) {
        S->sm_m[tid] = -INFINITY;
        S->sm_l[tid] = 0.0f;
    }
    float acc[4][4] = {};  // [ni][4]; warp rows wm*16+g{,+8}, cols wn*32+ni*8
    __syncthreads();

    for (int k0 = 0; k0 < TT; k0 += 64) {
        // load K tile transposed into ks[f][k] (aliases Ps) + V tile (tf32 hi)
#pragma unroll
        for (int c0 = 0; c0 < 64; c0 += 16) {
            const float4 vb = *(const float4*)&kp[(size_t)(k0 + ar) * EE + c0 + ac4];
            ks[c0 + ac4 + 0][ar] = vb.x;
            ks[c0 + ac4 + 1][ar] = vb.y;
            ks[c0 + ac4 + 2][ar] = vb.z;
            ks[c0 + ac4 + 3][ar] = vb.w;
        }
        {
            int vr = tid >> 2;
            int vc = (tid & 3) * 16;
#pragma unroll
            for (int j = 0; j < 4; j++) {
                const float4 v = *(const float4*)&vp[(size_t)(k0 + vr) * EE + vc + j * 4];
                uint4 t;
                t.x = f2tf(v.x); t.y = f2tf(v.y); t.z = f2tf(v.z); t.w = f2tf(v.w);
                *(uint4*)&S->vhi[vr][vc + j * 4] = t;
            }
        }
        __syncthreads();

        // scores: 4 rows x 4 cols per thread, ascending f (FROZEN fp32 chain)
        float s[4][4] = {};
#pragma unroll
        for (int f = 0; f < 64; f++) {
            float a[4], bv[4];
            *(float4*)&a[0] = *(const float4*)&S->qs[f][ty * 4];
            *(float4*)&bv[0] = *(const float4*)&ks[f][tx * 4];
#pragma unroll
            for (int i = 0; i < 4; i++)
#pragma unroll
                for (int j = 0; j < 4; j++) s[i][j] += a[i] * bv[j];
        }
        // mask + scale (identical expression)
#pragma unroll
        for (int i = 0; i < 4; i++) {
            int qg = q0 + ty * 4 + i;
#pragma unroll
            for (int j = 0; j < 4; j++) {
                int kg = k0 + tx * 4 + j;
                float m = (kg > qg) ? (1.0f - 1.0e9f) : 1.0f;
                s[i][j] = s[i][j] * m * 0.125f;
            }
        }
        // tile row max (local 4 + 16-lane tree; exact)
        float tm[4];
#pragma unroll
        for (int i = 0; i < 4; i++) {
            float v = fmaxf(fmaxf(s[i][0], s[i][1]), fmaxf(s[i][2], s[i][3]));
#pragma unroll
            for (int o = 8; o > 0; o >>= 1) v = fmaxf(v, __shfl_xor_sync(0xffffffffu, v, o));
            tm[i] = v;
        }
        if (tx == 0) {
#pragma unroll
            for (int i = 0; i < 4; i++) {
                int row = ty * 4 + i;
                float mo = S->sm_m[row];
                float mn = fmaxf(mo, tm[i]);
                S->sm_sc[row] = __expf(mo - mn);
                S->sm_m[row] = mn;
            }
        }
        __syncthreads();  // fences ks reads before Ps overwrite + sm publish

        // P = exp(s - m_new); bit-exact underflow skip at -104
        unsigned hm = (lane & 16) ? 0xffff0000u : 0x0000ffffu;
#pragma unroll
        for (int i = 0; i < 4; i++) {
            int row = ty * 4 + i;
            float mn = S->sm_m[row];
            if (tm[i] - mn > -104.0f) {
                float p0 = __expf(s[i][0] - mn);
                float p1 = __expf(s[i][1] - mn);
                float p2 = __expf(s[i][2] - mn);
                float p3 = __expf(s[i][3] - mn);
                float rs = p0 + p1 + p2 + p3;
                *(uint4*)&S->Ps[row][tx * 4] =
                    make_uint4(f2tf(p0), f2tf(p1), f2tf(p2), f2tf(p3));
#pragma unroll
                for (int o = 8; o > 0; o >>= 1) rs += __shfl_xor_sync(hm, rs, o);
                if (tx == 0) S->sm_l[row] = S->sm_l[row] * S->sm_sc[row] + rs;
            } else {
                *(uint4*)&S->Ps[row][tx * 4] = make_uint4(0, 0, 0, 0);
            }
        }
        __syncthreads();

        // rescale O accumulators, then PV mma (1xTF32)
        {
            float s0 = S->sm_sc[wm * 16 + g], s1 = S->sm_sc[wm * 16 + g + 8];
#pragma unroll
            for (int ni = 0; ni < 4; ni++) {
                acc[ni][0] *= s0; acc[ni][1] *= s0;
                acc[ni][2] *= s1; acc[ni][3] *= s1;
            }
        }
#pragma unroll
        for (int kk = 0; kk < 64; kk += 8) {
            uint32_t af[4];
            int mb = wm * 16 + g;
            af[0] = S->Ps[mb][kk + tig];
            af[1] = S->Ps[mb + 8][kk + tig];
            af[2] = S->Ps[mb][kk + tig + 4];
            af[3] = S->Ps[mb + 8][kk + tig + 4];
#pragma unroll
            for (int ni = 0; ni < 4; ni++) {
                int nb = wn * 32 + ni * 8 + g;
                uint32_t bf[2];
                bf[0] = S->vhi[kk + tig][nb];
                bf[1] = S->vhi[kk + tig + 4][nb];
                mma8(acc[ni], af, bf);
            }
        }
        __syncthreads();
    }
    // epilogue: O /= l, write transposed tf32 directly into g_athi [E][T]
    {
        float i0 = 1.0f / S->sm_l[wm * 16 + g];
        float i1 = 1.0f / S->sm_l[wm * 16 + g + 8];
        int m = q0 + wm * 16 + g;
        size_t obase = (size_t)b * EE * TT + (size_t)h * 64 * TT;
#pragma unroll
        for (int ni = 0; ni < 4; ni++) {
            int n = wn * 32 + ni * 8 + tig * 2;
            g_athi[obase + (size_t)n * TT + m] = f2tf(acc[ni][0] * i0);
            g_athi[obase + (size_t)(n + 1) * TT + m] = f2tf(acc[ni][1] * i0);
            g_athi[obase + (size_t)n * TT + m + 8] = f2tf(acc[ni][2] * i1);
            g_athi[obase + (size_t)(n + 1) * TT + m + 8] = f2tf(acc[ni][3] * i1);
        }
    }
}

// ---------------- LayerNorm over whole [T,E] plane per batch -----------------
__global__ __launch_bounds__(256) void ln_reduce(const float* __restrict__ in1,
                                                 const float* __restrict__ in2) {
    int b = blockIdx.y;
    const float* p1 = in1 + (size_t)b * LN_N;
    const float* p2 = in2 + (size_t)b * LN_N;
    const int chunk = (int)(LN_N / 64);
    size_t base = (size_t)blockIdx.x * chunk;
    double s = 0.0, sq = 0.0;
    for (int i = threadIdx.x * 4; i < chunk; i += 256 * 4) {
        float4 a = *(const float4*)&p1[base + i];
        float4 c = *(const float4*)&p2[base + i];
        float x0 = a.x + c.x, x1 = a.y + c.y, x2 = a.z + c.z, x3 = a.w + c.w;
        s += (double)x0 + (double)x1 + (double)x2 + (double)x3;
        sq += (double)x0 * x0 + (double)x1 * x1 + (double)x2 * x2 + (double)x3 * x3;
    }
    __shared__ double sh[256], shq[256];
    int tid = threadIdx.x;
    sh[tid] = s;
    shq[tid] = sq;
    __syncthreads();
    for (int o = 128; o > 0; o >>= 1) {
        if (tid < o) {
            sh[tid] += sh[tid + o];
            shq[tid] += shq[tid + o];
        }
        __syncthreads();
    }
    if (tid == 0) {
        g_part[(b * 64 + blockIdx.x) * 2] = sh[0];
        g_part[(b * 64 + blockIdx.x) * 2 + 1] = shq[0];
    }
}

__global__ void ln_finalize() {
    int b = blockIdx.x;
    int tid = threadIdx.x;
    __shared__ double sh[64], shq[64];
    sh[tid] = g_part[(b * 64 + tid) * 2];
    shq[tid] = g_part[(b * 64 + tid) * 2 + 1];
    __syncthreads();
    for (int o = 32; o > 0; o >>= 1) {
        if (tid < o) {
            sh[tid] += sh[tid + o];
            shq[tid] += shq[tid + o];
        }
        __syncthreads();
    }
    if (tid == 0) {
        double n = (double)LN_N;
        double mean = sh[0] / n;
        double var = shq[0] / n - mean * mean;
        g_stats[b * 2] = (float)mean;
        g_stats[b * 2 + 1] = (float)(1.0 / sqrt(var + 1e-5));
    }
}

__global__ __launch_bounds__(256) void ln_norm(const float* __restrict__ in1,
                                               const float* __restrict__ in2,
                                               const float* __restrict__ w,
                                               const float* __restrict__ bia,
                                               float* __restrict__ out) {
    size_t i = ((size_t)blockIdx.x * blockDim.x + threadIdx.x) * 4;
    if (i >= (size_t)BB * LN_N) return;
    int b = (int)(i / LN_N);
    size_t te = i % LN_N;
    float mean = g_stats[b * 2];
    float rstd = g_stats[b * 2 + 1];
    float4 a = *(const float4*)&in1[i];
    float4 c = *(const float4*)&in2[i];
    float4 ww = *(const float4*)&w[te];
    float4 bb = *(const float4*)&bia[te];
    float4 o;
    o.x = (a.x + c.x - mean) * rstd * ww.x + bb.x;
    o.y = (a.y + c.y - mean) * rstd * ww.y + bb.y;
    o.z = (a.z + c.z - mean) * rstd * ww.z + bb.z;
    o.w = (a.w + c.w - mean) * rstd * ww.w + bb.w;
    *(float4*)&out[i] = o;
}

// ---------------- launch -----------------------------------------------------
extern "C" void kernel_launch(void* const* d_in, const int* in_sizes, int n_in,
                              void* d_out, int out_size) {
    const float* x = (const float*)d_in[0];
    const float* q_w = (const float*)d_in[1];
    const float* k_w = (const float*)d_in[2];
    const float* v_w = (const float*)d_in[3];
    const float* fr_w = (const float*)d_in[4];
    const float* ff_w = (const float*)d_in[5];
    const float* ff_b = (const float*)d_in[6];
    const float* ln1_w = (const float*)d_in[7];
    const float* ln1_b = (const float*)d_in[8];
    const float* ln2_w = (const float*)d_in[9];
    const float* ln2_b = (const float*)d_in[10];
    float* out = (float*)d_out;

    float *p_wq, *p_wk, *p_q, *p_k, *p_v, *p_zf, *p_z1, *p_z2;
    uint32_t *p_wvhi, *p_wffhi, *p_frhi, *p_athi;
    cudaGetSymbolAddress((void**)&p_wq, g_wq);
    cudaGetSymbolAddress((void**)&p_wk, g_wk);
    cudaGetSymbolAddress((void**)&p_q, g_q);
    cudaGetSymbolAddress((void**)&p_k, g_k);
    cudaGetSymbolAddress((void**)&p_v, g_v);
    cudaGetSymbolAddress((void**)&p_zf, g_zf);
    cudaGetSymbolAddress((void**)&p_z1, g_z1);
    cudaGetSymbolAddress((void**)&p_z2, g_z2);
    cudaGetSymbolAddress((void**)&p_wvhi, g_wvhi);
    cudaGetSymbolAddress((void**)&p_wffhi, g_wffhi);
    cudaGetSymbolAddress((void**)&p_frhi, g_frhi);
    cudaGetSymbolAddress((void**)&p_athi, g_athi);

    const size_t SMP = 3 * T1_STAGE_U32 * sizeof(uint32_t);  // 52224 B
    const size_t SMA = sizeof(AttnSmem);                     // 54016 B
    cudaFuncSetAttribute(attn_fused, cudaFuncAttributeMaxDynamicSharedMemorySize, (int)SMA);
    cudaFuncSetAttribute(gemm_qkv, cudaFuncAttributeMaxDynamicSharedMemorySize, (int)SMP);
    cudaFuncSetAttribute(gemm_tf1<false>, cudaFuncAttributeMaxDynamicSharedMemorySize, (int)SMP);
    cudaFuncSetAttribute(gemm_tf1<true>, cudaFuncAttributeMaxDynamicSharedMemorySize, (int)SMP);

    // 1) merged weight repacks
    int repack_total = EE * EE + BB * EE * EE;
    repack_all<<<(repack_total + 255) / 256, 256>>>(q_w, k_w, v_w, ff_w, fr_w);

    // 2) transpose x (feeds V path of merged kernel)
    dim3 gtx(EE / 32, (BB * TT) / 32, 1);
    transpose_tf<<<gtx, 256>>>(x, p_athi, BB * TT, EE);

    // 3) merged QKV: z=0,1 exact fp32 Q/K; z=2 tensor-core V fills the tail
    dim3 gqkv(EE / 128, (BB * TT) / 128, 3);
    gemm_qkv<<<gqkv, 256, SMP>>>(x, p_wq, p_wk, p_q, p_k,
                                 p_athi, p_wvhi, p_v, BB * TT, EE, EE);

    // 4) fused attention (writes transposed tf32 athi directly)
    dim3 gat(TT / 64, BB * HH, 1);
    attn_fused<<<gat, 256, SMA>>>();

    // 5) zf[b] = zm[b] @ fr[b] (1xTF32, batched; A = athi from attn epilogue)
    dim3 gfr(EE / 128, TT / 128, BB);
    gemm_tf1<false><<<gfr, 256, SMP>>>(p_athi, p_frhi, p_zf,
                                       TT, EE, EE, (long)TT * EE, (long)EE * EE,
                                       (long)TT * EE, nullptr);

    // 6) LN1 over x + zf -> z1
    dim3 gred(64, BB, 1);
    ln_reduce<<<gred, 256>>>(x, p_zf);
    ln_finalize<<<BB, 64>>>();
    size_t total = (size_t)BB * LN_N;
    ln_norm<<<(unsigned)((total / 4 + 255) / 256), 256>>>(x, p_zf, ln1_w, ln1_b, p_z1);

    // 7) FFN: z2 = relu(z1 @ ff_w^T + ff_b) (1xTF32)
    transpose_tf<<<gtx, 256>>>(p_z1, p_athi, BB * TT, EE);
    dim3 gv(EE / 128, (BB * TT) / 128, 1);
    gemm_tf1<true><<<gv, 256, SMP>>>(p_athi, p_wffhi, p_z2,
                                     BB * TT, EE, EE, 0, 0, 0, ff_b);

    // 8) LN2 over z1 + z2 -> out
    ln_reduce<<<gred, 256>>>(p_z1, p_z2);
    ln_finalize<<<BB, 64>>>();
    ln_norm<<<(unsigned)((total / 4 + 255) / 256), 256>>>(p_z1, p_z2, ln2_w, ln2_b, out);
}

// round 14
// speedup vs baseline: 1.0514x; 1.0514x over previous
#include <cuda_runtime.h>
#include <math.h>
#include <stdint.h>

#define BB 4
#define TT 1024
#define EE 1024
#define HH 16
#define FFDIM 64
#define LN_N ((size_t)TT * EE)

// ---------------- scratch (static device globals; no allocation) -------------
__device__ float g_wq[EE * EE];
__device__ float g_wk[EE * EE];
__device__ float g_q[BB * TT * EE];
__device__ float g_k[BB * TT * EE];
__device__ float g_v[BB * TT * EE];
__device__ float g_zf[BB * TT * EE];
__device__ float g_z1[BB * TT * EE];
__device__ float g_z2[BB * TT * EE];
__device__ double g_part[BB * 64 * 2];
__device__ float g_stats[BB * 2];
__device__ uint32_t g_wvhi[EE * EE];
__device__ uint32_t g_wffhi[EE * EE];
__device__ uint32_t g_frhi[BB * EE * EE];
__device__ uint32_t g_athi[BB * TT * EE];  // transposed activation [K][M]

// ---------------- helpers ----------------------------------------------------
__device__ __forceinline__ uint32_t f2tf(float x) {
    uint32_t r;
    asm("cvt.rna.tf32.f32 %0, %1;" : "=r"(r) : "f"(x));
    return r;
}

__device__ __forceinline__ void mma8(float c[4], const uint32_t a[4], const uint32_t b[2]) {
    asm volatile(
        "mma.sync.aligned.m16n8k8.row.col.f32.tf32.tf32.f32 "
        "{%0,%1,%2,%3}, {%4,%5,%6,%7}, {%8,%9}, {%0,%1,%2,%3};\n"
        : "+f"(c[0]), "+f"(c[1]), "+f"(c[2]), "+f"(c[3])
        : "r"(a[0]), "r"(a[1]), "r"(a[2]), "r"(a[3]), "r"(b[0]), "r"(b[1]));
}

__device__ __forceinline__ uint32_t smem_u32(const void* p) {
    return (uint32_t)__cvta_generic_to_shared(p);
}
__device__ __forceinline__ void cpasync16(uint32_t dst, const void* src) {
    asm volatile("cp.async.ca.shared.global [%0], [%1], 16;\n" ::"r"(dst), "l"(src));
}

// ---------------- merged weight repacks --------------------------------------
__global__ void repack_all(const float* __restrict__ qw,
                           const float* __restrict__ kw,
                           const float* __restrict__ vw,
                           const float* __restrict__ ffw,
                           const float* __restrict__ frw) {
    int idx = blockIdx.x * blockDim.x + threadIdx.x;
    if (idx < EE * EE) {
        int e = idx / EE, n = idx % EE;
        int h = n >> 6, f = n & 63;
        int src = h * (EE * FFDIM) + e * FFDIM + f;
        g_wq[idx] = qw[src];
        g_wk[idx] = kw[src];
        g_wvhi[idx] = f2tf(vw[src]);
        g_wffhi[idx] = f2tf(ffw[n * EE + e]);
    }
    int idx2 = idx - EE * EE;
    if (idx2 >= 0 && idx2 < BB * EE * EE) g_frhi[idx2] = f2tf(frw[idx2]);
}

// ---------------- tiled transpose + tf32: [M][K] -> [K][M] -------------------
__global__ __launch_bounds__(256) void transpose_tf(
    const float* __restrict__ in, uint32_t* __restrict__ ohi, int M, int K) {
    __shared__ float t[32][33];
    int m0 = blockIdx.y * 32, k0 = blockIdx.x * 32;
    int tx = threadIdx.x & 31, ty = threadIdx.x >> 5;
#pragma unroll
    for (int i = ty; i < 32; i += 8) t[i][tx] = in[(size_t)(m0 + i) * K + k0 + tx];
    __syncthreads();
#pragma unroll
    for (int i = ty; i < 32; i += 8) {
        ohi[(size_t)(k0 + i) * M + m0 + tx] = f2tf(t[tx][i]);
    }
}

// ---------------- merged QKV GEMM (FROZEN fp32 chain for Q,K) ----------------
#define T1_STAGE_U32 (2 * 16 * 136)
__global__ __launch_bounds__(256, 2) void gemm_qkv(
    const float* __restrict__ A, const float* __restrict__ B0,
    const float* __restrict__ B1, float* __restrict__ C0, float* __restrict__ C1,
    const uint32_t* __restrict__ Ahi, const uint32_t* __restrict__ Bhi,
    float* __restrict__ CV, int M, int N, int K) {
    extern __shared__ uint32_t smp[];
    int m0 = blockIdx.y * 128, n0 = blockIdx.x * 128;
    int tid = threadIdx.x;

    if (blockIdx.z < 2) {
        const float* Bm = blockIdx.z ? B1 : B0;
        float* C = blockIdx.z ? C1 : C0;
        float* Asf = (float*)smp;             // [2][16][132]
        float* Bsf = Asf + 2 * 16 * 132;      // [2][16][128]
        int ty = tid >> 4, tx = tid & 15;
        float acc[8][8] = {};
        int ar = tid >> 2;
        int ac4 = (tid & 3) * 4;
        int bk = tid >> 5;
        int bc4 = (tid & 31) * 4;

        uint32_t bd0[2], bd1[2];
        bd0[0] = smem_u32(&Bsf[0 * 2048 + bk * 128 + bc4]);
        bd0[1] = smem_u32(&Bsf[1 * 2048 + bk * 128 + bc4]);
        bd1[0] = smem_u32(&Bsf[0 * 2048 + (bk + 8) * 128 + bc4]);
        bd1[1] = smem_u32(&Bsf[1 * 2048 + (bk + 8) * 128 + bc4]);

        cpasync16(bd0[0], &Bm[(size_t)bk * N + n0 + bc4]);
        cpasync16(bd1[0], &Bm[(size_t)(bk + 8) * N + n0 + bc4]);
        asm volatile("cp.async.commit_group;\n");
        float4 ra0 = *(const float4*)&A[(size_t)(m0 + ar) * K + ac4];
        float4 ra1 = *(const float4*)&A[(size_t)(m0 + ar + 64) * K + ac4];
        Asf[(ac4 + 0) * 132 + ar] = ra0.x; Asf[(ac4 + 1) * 132 + ar] = ra0.y;
        Asf[(ac4 + 2) * 132 + ar] = ra0.z; Asf[(ac4 + 3) * 132 + ar] = ra0.w;
        Asf[(ac4 + 0) * 132 + ar + 64] = ra1.x; Asf[(ac4 + 1) * 132 + ar + 64] = ra1.y;
        Asf[(ac4 + 2) * 132 + ar + 64] = ra1.z; Asf[(ac4 + 3) * 132 + ar + 64] = ra1.w;
        asm volatile("cp.async.wait_group 0;\n");
        __syncthreads();

        int nt = K / 16;
        for (int t = 0; t < nt; t++) {
            int s = t & 1;
            if (t + 1 < nt) {
                int k0 = (t + 1) * 16;
                cpasync16(bd0[s ^ 1], &Bm[(size_t)(k0 + bk) * N + n0 + bc4]);
                cpasync16(bd1[s ^ 1], &Bm[(size_t)(k0 + bk + 8) * N + n0 + bc4]);
                asm volatile("cp.async.commit_group;\n");
                ra0 = *(const float4*)&A[(size_t)(m0 + ar) * K + k0 + ac4];
                ra1 = *(const float4*)&A[(size_t)(m0 + ar + 64) * K + k0 + ac4];
            }
            const float* Asc = Asf + s * 2112;
            const float* Bsc = Bsf + s * 2048;
#pragma unroll
            for (int k = 0; k < 16; k++) {
                float a[8], b[8];
                *(float4*)&a[0] = *(const float4*)&Asc[k * 132 + ty * 8];
                *(float4*)&a[4] = *(const float4*)&Asc[k * 132 + ty * 8 + 4];
                *(float4*)&b[0] = *(const float4*)&Bsc[k * 128 + tx * 8];
                *(float4*)&b[4] = *(const float4*)&Bsc[k * 128 + tx * 8 + 4];
#pragma unroll
                for (int i = 0; i < 8; i++)
#pragma unroll
                    for (int j = 0; j < 8; j++) acc[i][j] += a[i] * b[j];
            }
            if (t + 1 < nt) {
                int s2 = s ^ 1;
                float* Asn = Asf + s2 * 2112;
                Asn[(ac4 + 0) * 132 + ar] = ra0.x; Asn[(ac4 + 1) * 132 + ar] = ra0.y;
                Asn[(ac4 + 2) * 132 + ar] = ra0.z; Asn[(ac4 + 3) * 132 + ar] = ra0.w;
                Asn[(ac4 + 0) * 132 + ar + 64] = ra1.x; Asn[(ac4 + 1) * 132 + ar + 64] = ra1.y;
                Asn[(ac4 + 2) * 132 + ar + 64] = ra1.z; Asn[(ac4 + 3) * 132 + ar + 64] = ra1.w;
                asm volatile("cp.async.wait_group 0;\n");
            }
            __syncthreads();
        }
#pragma unroll
        for (int i = 0; i < 8; i++) {
            int m = m0 + ty * 8 + i;
            *(float4*)&C[(size_t)m * N + n0 + tx * 8] = *(float4*)&acc[i][0];
            *(float4*)&C[(size_t)m * N + n0 + tx * 8 + 4] = *(float4*)&acc[i][4];
        }
    } else {
        // 1xTF32 tensor path (V projection)
        int lane = tid & 31, w = tid >> 5;
        int wm = w & 1, wn = w >> 1;
        int g = lane >> 2, tig = lane & 3;
        float acc[4][4][4] = {};
        int crow = tid >> 4;
        int col0 = (tid & 15) * 4;
        uint32_t sbase = smem_u32(smp);
        const uint32_t STAGE_B = T1_STAGE_U32 * 4;
        uint32_t offA = ((0 * 16 + crow) * 136 + col0) * 4;
        uint32_t offB = ((1 * 16 + crow) * 136 + col0) * 4;

        int nt = K / 16;
#pragma unroll
        for (int p = 0; p < 2; p++) {
            uint32_t dst = sbase + p * STAGE_B;
            const uint32_t* ga = &Ahi[(size_t)(p * 16 + crow) * M + m0 + col0];
            const uint32_t* gb = &Bhi[(size_t)(p * 16 + crow) * N + n0 + col0];
            cpasync16(dst + offA, ga);
            cpasync16(dst + offA + 256, ga + 64);
            cpasync16(dst + offB, gb);
            cpasync16(dst + offB + 256, gb + 64);
            asm volatile("cp.async.commit_group;\n");
        }
        asm volatile("cp.async.wait_group 1;\n");
        __syncthreads();

        int sl = 2, sc = 0;
        for (int t = 0; t < nt; t++) {
            if (t + 2 < nt) {
                uint32_t dst = sbase + sl * STAGE_B;
                const uint32_t* ga = &Ahi[(size_t)((t + 2) * 16 + crow) * M + m0 + col0];
                const uint32_t* gb = &Bhi[(size_t)((t + 2) * 16 + crow) * N + n0 + col0];
                cpasync16(dst + offA, ga);
                cpasync16(dst + offA + 256, ga + 64);
                cpasync16(dst + offB, gb);
                cpasync16(dst + offB + 256, gb + 64);
            }
            asm volatile("cp.async.commit_group;\n");
            const uint32_t* As = smp + sc * T1_STAGE_U32;
            const uint32_t* Bs = As + 16 * 136;
#pragma unroll
            for (int kk = 0; kk < 16; kk += 8) {
                uint32_t af[4][4];
#pragma unroll
                for (int mi = 0; mi < 4; mi++) {
                    int mb = wm * 64 + mi * 16 + g;
                    af[mi][0] = As[(kk + tig) * 136 + mb];
                    af[mi][1] = As[(kk + tig) * 136 + mb + 8];
                    af[mi][2] = As[(kk + tig + 4) * 136 + mb];
                    af[mi][3] = As[(kk + tig + 4) * 136 + mb + 8];
                }
#pragma unroll
                for (int ni = 0; ni < 4; ni++) {
                    int nb = wn * 32 + ni * 8 + g;
                    uint32_t bf[2];
                    bf[0] = Bs[(kk + tig) * 136 + nb];
                    bf[1] = Bs[(kk + tig + 4) * 136 + nb];
#pragma unroll
                    for (int mi = 0; mi < 4; mi++) mma8(acc[mi][ni], af[mi], bf);
                }
            }
            asm volatile("cp.async.wait_group 1;\n");
            __syncthreads();
            sl = (sl == 2) ? 0 : sl + 1;
            sc = (sc == 2) ? 0 : sc + 1;
        }
#pragma unroll
        for (int mi = 0; mi < 4; mi++) {
            int m = m0 + wm * 64 + mi * 16 + g;
#pragma unroll
            for (int ni = 0; ni < 4; ni++) {
                int n = n0 + wn * 32 + ni * 8 + tig * 2;
                *(float2*)&CV[(size_t)m * N + n] =
                    make_float2(acc[mi][ni][0], acc[mi][ni][1]);
                *(float2*)&CV[(size_t)(m + 8) * N + n] =
                    make_float2(acc[mi][ni][2], acc[mi][ni][3]);
            }
        }
    }
}

// ---------------- 1xTF32 tensor-core GEMM, 3-stage cp.async pipeline ---------
template <bool RELU>
__global__ __launch_bounds__(256, 2) void gemm_tf1(
    const uint32_t* __restrict__ Ahi, const uint32_t* __restrict__ Bhi,
    float* __restrict__ C, int M, int N, int K,
    long sA, long sB, long sC, const float* __restrict__ bias) {
    extern __shared__ uint32_t smp[];
    Ahi += (size_t)blockIdx.z * sA;
    Bhi += (size_t)blockIdx.z * sB;
    C += (size_t)blockIdx.z * sC;
    int m0 = blockIdx.y * 128, n0 = blockIdx.x * 128;
    int tid = threadIdx.x, lane = tid & 31, w = tid >> 5;
    int wm = w & 1, wn = w >> 1;
    int g = lane >> 2, tig = lane & 3;
    float acc[4][4][4] = {};

    int crow = tid >> 4;
    int col0 = (tid & 15) * 4;
    uint32_t sbase = smem_u32(smp);
    const uint32_t STAGE_B = T1_STAGE_U32 * 4;
    uint32_t offA = ((0 * 16 + crow) * 136 + col0) * 4;
    uint32_t offB = ((1 * 16 + crow) * 136 + col0) * 4;

    int nt = K / 16;
#pragma unroll
    for (int p = 0; p < 2; p++) {
        uint32_t dst = sbase + p * STAGE_B;
        const uint32_t* ga = &Ahi[(size_t)(p * 16 + crow) * M + m0 + col0];
        const uint32_t* gb = &Bhi[(size_t)(p * 16 + crow) * N + n0 + col0];
        cpasync16(dst + offA, ga);
        cpasync16(dst + offA + 256, ga + 64);
        cpasync16(dst + offB, gb);
        cpasync16(dst + offB + 256, gb + 64);
        asm volatile("cp.async.commit_group;\n");
    }
    asm volatile("cp.async.wait_group 1;\n");
    __syncthreads();

    int sl = 2, sc = 0;
    for (int t = 0; t < nt; t++) {
        if (t + 2 < nt) {
            uint32_t dst = sbase + sl * STAGE_B;
            const uint32_t* ga = &Ahi[(size_t)((t + 2) * 16 + crow) * M + m0 + col0];
            const uint32_t* gb = &Bhi[(size_t)((t + 2) * 16 + crow) * N + n0 + col0];
            cpasync16(dst + offA, ga);
            cpasync16(dst + offA + 256, ga + 64);
            cpasync16(dst + offB, gb);
            cpasync16(dst + offB + 256, gb + 64);
        }
        asm volatile("cp.async.commit_group;\n");
        const uint32_t* As = smp + sc * T1_STAGE_U32;
        const uint32_t* Bs = As + 16 * 136;
#pragma unroll
        for (int kk = 0; kk < 16; kk += 8) {
            uint32_t af[4][4];
#pragma unroll
            for (int mi = 0; mi < 4; mi++) {
                int mb = wm * 64 + mi * 16 + g;
                af[mi][0] = As[(kk + tig) * 136 + mb];
                af[mi][1] = As[(kk + tig) * 136 + mb + 8];
                af[mi][2] = As[(kk + tig + 4) * 136 + mb];
                af[mi][3] = As[(kk + tig + 4) * 136 + mb + 8];
            }
#pragma unroll
            for (int ni = 0; ni < 4; ni++) {
                int nb = wn * 32 + ni * 8 + g;
                uint32_t bf[2];
                bf[0] = Bs[(kk + tig) * 136 + nb];
                bf[1] = Bs[(kk + tig + 4) * 136 + nb];
#pragma unroll
                for (int mi = 0; mi < 4; mi++) mma8(acc[mi][ni], af[mi], bf);
            }
        }
        asm volatile("cp.async.wait_group 1;\n");
        __syncthreads();
        sl = (sl == 2) ? 0 : sl + 1;
        sc = (sc == 2) ? 0 : sc + 1;
    }
#pragma unroll
    for (int mi = 0; mi < 4; mi++) {
        int m = m0 + wm * 64 + mi * 16 + g;
#pragma unroll
        for (int ni = 0; ni < 4; ni++) {
            int n = n0 + wn * 32 + ni * 8 + tig * 2;
            float b0 = bias ? bias[n] : 0.0f;
            float b1 = bias ? bias[n + 1] : 0.0f;
            float v0 = acc[mi][ni][0] + b0, v1 = acc[mi][ni][1] + b1;
            float v2 = acc[mi][ni][2] + b0, v3 = acc[mi][ni][3] + b1;
            if (RELU) {
                v0 = fmaxf(v0, 0.0f); v1 = fmaxf(v1, 0.0f);
                v2 = fmaxf(v2, 0.0f); v3 = fmaxf(v3, 0.0f);
            }
            *(float2*)&C[(size_t)m * N + n] = make_float2(v0, v1);
            *(float2*)&C[(size_t)(m + 8) * N + n] = make_float2(v2, v3);
        }
    }
}

// ---------------- fused attention, BQ=128 BK=64, 2 blocks/SM -----------------
// Scores: FROZEN ascending-f fp32 fma + identical mask. 8x4 thread tile
// (LDS-lean). K/V of the NEXT tile are prefetched into registers during the
// scores phase. PV is 1xTF32 (validated in R12). Epilogue writes transposed
// tf32 athi directly.
struct __align__(16) AttnSmem {
    float qs[64][132];      // [f][q]    33792 B
    uint32_t Ps[128][68];   // [q][k]; rows 0-63 alias ks[f][k]  34816 B
    uint32_t vhi[64][72];   // [k][f] tf32                       18432 B
    float sm_m[128];
    float sm_l[128];
    float sm_sc[128];       //                                    1536 B
};                          // total 88576 B -> 2 blocks/SM

__global__ __launch_bounds__(256, 2) void attn_fused() {
    extern __shared__ char smraw[];
    AttnSmem* S = (AttnSmem*)smraw;
    float(*ks)[68] = (float(*)[68])S->Ps;
    int bh = blockIdx.y;
    int b = bh / HH, h = bh % HH;
    int q0 = blockIdx.x * 128;
    const float* qp = g_q + (size_t)b * TT * EE + h * FFDIM;
    const float* kp = g_k + (size_t)b * TT * EE + h * FFDIM;
    const float* vp = g_v + (size_t)b * TT * EE + h * FFDIM;

    int tid = threadIdx.x;
    int ty = tid >> 4, tx = tid & 15;
    int lane = tid & 31, w = tid >> 5;
    int wm = w >> 1, wn = w & 1;
    int g = lane >> 2, tig = lane & 3;
    int ar = tid >> 2;            // 0..63
    int ac4 = (tid & 3) * 4;
    int vr = tid >> 2;            // 0..63
    int vc = (tid & 3) * 16;      // 0,16,32,48

    // load Q tile (once): 128 q-rows x 64 f -> qs[f][q]
#pragma unroll
    for (int c0 = 0; c0 < 64; c0 += 16) {
#pragma unroll
        for (int ri = 0; ri < 2; ri++) {
            int r = ar + ri * 64;
            const float4 va = *(const float4*)&qp[(size_t)(q0 + r) * EE + c0 + ac4];
            S->qs[c0 + ac4 + 0][r] = va.x;
            S->qs[c0 + ac4 + 1][r] = va.y;
            S->qs[c0 + ac4 + 2][r] = va.z;
            S->qs[c0 + ac4 + 3][r] = va.w;
        }
    }
    if (tid < 128) {
        S->sm_m[tid] = -INFINITY;
        S->sm_l[tid] = 0.0f;
    }
    // prologue: tile 0 K,V direct into smem
#pragma unroll
    for (int c = 0; c < 4; c++) {
        const float4 vb = *(const float4*)&kp[(size_t)ar * EE + c * 16 + ac4];
        ks[c * 16 + ac4 + 0][ar] = vb.x;
        ks[c * 16 + ac4 + 1][ar] = vb.y;
        ks[c * 16 + ac4 + 2][ar] = vb.z;
        ks[c * 16 + ac4 + 3][ar] = vb.w;
    }
#pragma unroll
    for (int j = 0; j < 4; j++) {
        const float4 v = *(const float4*)&vp[(size_t)vr * EE + vc + j * 4];
        uint4 t;
        t.x = f2tf(v.x); t.y = f2tf(v.y); t.z = f2tf(v.z); t.w = f2tf(v.w);
        *(uint4*)&S->vhi[vr][vc + j * 4] = t;
    }
    float acc[2][4][4] = {};
    __syncthreads();

    for (int k0 = 0; k0 < TT; k0 += 64) {
        bool more = (k0 + 64 < TT);
        float4 kr[4], vrg[4];
        if (more) {  // prefetch next K/V tile into registers (overlaps scores)
#pragma unroll
            for (int c = 0; c < 4; c++)
                kr[c] = *(const float4*)&kp[(size_t)(k0 + 64 + ar) * EE + c * 16 + ac4];
#pragma unroll
            for (int j = 0; j < 4; j++)
                vrg[j] = *(const float4*)&vp[(size_t)(k0 + 64 + vr) * EE + vc + j * 4];
        }

        // scores: 8 rows x 4 cols, ascending f (FROZEN fp32 chain)
        float s[8][4] = {};
#pragma unroll
        for (int f = 0; f < 64; f++) {
            float a[8], bv[4];
            *(float4*)&a[0] = *(const float4*)&S->qs[f][ty * 8];
            *(float4*)&a[4] = *(const float4*)&S->qs[f][ty * 8 + 4];
            *(float4*)&bv[0] = *(const float4*)&ks[f][tx * 4];
#pragma unroll
            for (int i = 0; i < 8; i++)
#pragma unroll
                for (int j = 0; j < 4; j++) s[i][j] += a[i] * bv[j];
        }
        // mask + scale (identical expression)
#pragma unroll
        for (int i = 0; i < 8; i++) {
            int qg = q0 + ty * 8 + i;
#pragma unroll
            for (int j = 0; j < 4; j++) {
                int kg = k0 + tx * 4 + j;
                float m = (kg > qg) ? (1.0f - 1.0e9f) : 1.0f;
                s[i][j] = s[i][j] * m * 0.125f;
            }
        }
        // tile row max
        float tm[8];
#pragma unroll
        for (int i = 0; i < 8; i++) {
            float v = fmaxf(fmaxf(s[i][0], s[i][1]), fmaxf(s[i][2], s[i][3]));
#pragma unroll
            for (int o = 8; o > 0; o >>= 1) v = fmaxf(v, __shfl_xor_sync(0xffffffffu, v, o));
            tm[i] = v;
        }
        if (tx == 0) {
#pragma unroll
            for (int i = 0; i < 8; i++) {
                int row = ty * 8 + i;
                float mo = S->sm_m[row];
                float mn = fmaxf(mo, tm[i]);
                S->sm_sc[row] = __expf(mo - mn);
                S->sm_m[row] = mn;
            }
        }
        __syncthreads();  // fences ks reads before Ps overwrite + sm publish

        // P = exp(s - m_new); bit-exact underflow skip at -104
        unsigned hm = (lane & 16) ? 0xffff0000u : 0x0000ffffu;
#pragma unroll
        for (int i = 0; i < 8; i++) {
            int row = ty * 8 + i;
            float mn = S->sm_m[row];
            if (tm[i] - mn > -104.0f) {
                float p0 = __expf(s[i][0] - mn);
                float p1 = __expf(s[i][1] - mn);
                float p2 = __expf(s[i][2] - mn);
                float p3 = __expf(s[i][3] - mn);
                float rs = p0 + p1 + p2 + p3;
                *(uint4*)&S->Ps[row][tx * 4] =
                    make_uint4(f2tf(p0), f2tf(p1), f2tf(p2), f2tf(p3));
#pragma unroll
                for (int o = 8; o > 0; o >>= 1) rs += __shfl_xor_sync(hm, rs, o);
                if (tx == 0) S->sm_l[row] = S->sm_l[row] * S->sm_sc[row] + rs;
            } else {
                *(uint4*)&S->Ps[row][tx * 4] = make_uint4(0, 0, 0, 0);
            }
        }
        __syncthreads();

        // rescale O accumulators, then PV mma (1xTF32)
#pragma unroll
        for (int mi = 0; mi < 2; mi++) {
            int row = wm * 32 + mi * 16 + g;
            float s0 = S->sm_sc[row], s1 = S->sm_sc[row + 8];
#pragma unroll
            for (int ni = 0; ni < 4; ni++) {
                acc[mi][ni][0] *= s0; acc[mi][ni][1] *= s0;
                acc[mi][ni][2] *= s1; acc[mi][ni][3] *= s1;
            }
        }
#pragma unroll
        for (int kk = 0; kk < 64; kk += 8) {
            uint32_t af[2][4];
#pragma unroll
            for (int mi = 0; mi < 2; mi++) {
                int mb = wm * 32 + mi * 16 + g;
                af[mi][0] = S->Ps[mb][kk + tig];
                af[mi][1] = S->Ps[mb + 8][kk + tig];
                af[mi][2] = S->Ps[mb][kk + tig + 4];
                af[mi][3] = S->Ps[mb + 8][kk + tig + 4];
            }
#pragma unroll
            for (int ni = 0; ni < 4; ni++) {
                int nb = wn * 32 + ni * 8 + g;
                uint32_t bf[2];
                bf[0] = S->vhi[kk + tig][nb];
                bf[1] = S->vhi[kk + tig + 4][nb];
#pragma unroll
                for (int mi = 0; mi < 2; mi++) mma8(acc[mi][ni], af[mi], bf);
            }
        }
        __syncthreads();  // fences Ps/vhi reads before next-tile stores

        if (more) {  // store prefetched K/V into smem
#pragma unroll
            for (int c = 0; c < 4; c++) {
                ks[c * 16 + ac4 + 0][ar] = kr[c].x;
                ks[c * 16 + ac4 + 1][ar] = kr[c].y;
                ks[c * 16 + ac4 + 2][ar] = kr[c].z;
                ks[c * 16 + ac4 + 3][ar] = kr[c].w;
            }
#pragma unroll
            for (int j = 0; j < 4; j++) {
                uint4 t;
                t.x = f2tf(vrg[j].x); t.y = f2tf(vrg[j].y);
                t.z = f2tf(vrg[j].z); t.w = f2tf(vrg[j].w);
                *(uint4*)&S->vhi[vr][vc + j * 4] = t;
            }
        }
        __syncthreads();
    }
    // epilogue: O /= l, write transposed tf32 directly into g_athi [B][E][T]
    {
        size_t obase = (size_t)b * EE * TT + (size_t)h * 64 * TT;
#pragma unroll
        for (int mi = 0; mi < 2; mi++) {
            int row = wm * 32 + mi * 16 + g;
            float i0 = 1.0f / S->sm_l[row];
            float i1 = 1.0f / S->sm_l[row + 8];
            int m = q0 + row;
#pragma unroll
            for (int ni = 0; ni < 4; ni++) {
                int n = wn * 32 + ni * 8 + tig * 2;
                g_athi[obase + (size_t)n * TT + m] = f2tf(acc[mi][ni][0] * i0);
                g_athi[obase + (size_t)(n + 1) * TT + m] = f2tf(acc[mi][ni][1] * i0);
                g_athi[obase + (size_t)n * TT + m + 8] = f2tf(acc[mi][ni][2] * i1);
                g_athi[obase + (size_t)(n + 1) * TT + m + 8] = f2tf(acc[mi][ni][3] * i1);
            }
        }
    }
}

// ---------------- LayerNorm over whole [T,E] plane per batch -----------------
__global__ __launch_bounds__(256) void ln_reduce(const float* __restrict__ in1,
                                                 const float* __restrict__ in2) {
    int b = blockIdx.y;
    const float* p1 = in1 + (size_t)b * LN_N;
    const float* p2 = in2 + (size_t)b * LN_N;
    const int chunk = (int)(LN_N / 64);
    size_t base = (size_t)blockIdx.x * chunk;
    double s = 0.0, sq = 0.0;
    for (int i = threadIdx.x * 4; i < chunk; i += 256 * 4) {
        float4 a = *(const float4*)&p1[base + i];
        float4 c = *(const float4*)&p2[base + i];
        float x0 = a.x + c.x, x1 = a.y + c.y, x2 = a.z + c.z, x3 = a.w + c.w;
        s += (double)x0 + (double)x1 + (double)x2 + (double)x3;
        sq += (double)x0 * x0 + (double)x1 * x1 + (double)x2 * x2 + (double)x3 * x3;
    }
    __shared__ double sh[256], shq[256];
    int tid = threadIdx.x;
    sh[tid] = s;
    shq[tid] = sq;
    __syncthreads();
    for (int o = 128; o > 0; o >>= 1) {
        if (tid < o) {
            sh[tid] += sh[tid + o];
            shq[tid] += shq[tid + o];
        }
        __syncthreads();
    }
    if (tid == 0) {
        g_part[(b * 64 + blockIdx.x) * 2] = sh[0];
        g_part[(b * 64 + blockIdx.x) * 2 + 1] = shq[0];
    }
}

__global__ void ln_finalize() {
    int b = blockIdx.x;
    int tid = threadIdx.x;
    __shared__ double sh[64], shq[64];
    sh[tid] = g_part[(b * 64 + tid) * 2];
    shq[tid] = g_part[(b * 64 + tid) * 2 + 1];
    __syncthreads();
    for (int o = 32; o > 0; o >>= 1) {
        if (tid < o) {
            sh[tid] += sh[tid + o];
            shq[tid] += shq[tid + o];
        }
        __syncthreads();
    }
    if (tid == 0) {
        double n = (double)LN_N;
        double mean = sh[0] / n;
        double var = shq[0] / n - mean * mean;
        g_stats[b * 2] = (float)mean;
        g_stats[b * 2 + 1] = (float)(1.0 / sqrt(var + 1e-5));
    }
}

// LN1 fused with transpose: writes z1 (normal layout) AND transposed tf32 athi
__global__ __launch_bounds__(256) void ln_norm_t(
    const float* __restrict__ in1, const float* __restrict__ in2,
    const float* __restrict__ w, const float* __restrict__ bia,
    float* __restrict__ out, uint32_t* __restrict__ ohi) {
    __shared__ float t[32][33];
    int m0 = blockIdx.y * 32, k0 = blockIdx.x * 32;
    int tx = threadIdx.x & 31, ty = threadIdx.x >> 5;
    int b = m0 / TT;  // constant within tile (32 | 1024)
    float mean = g_stats[b * 2];
    float rstd = g_stats[b * 2 + 1];
#pragma unroll
    for (int i = ty; i < 32; i += 8) {
        int row = m0 + i;
        size_t idx = (size_t)row * EE + k0 + tx;
        size_t te = (size_t)(row % TT) * EE + k0 + tx;
        float v = (in1[idx] + in2[idx] - mean) * rstd * w[te] + bia[te];
        out[idx] = v;
        t[i][tx] = v;
    }
    __syncthreads();
#pragma unroll
    for (int i = ty; i < 32; i += 8) {
        ohi[(size_t)(k0 + i) * (BB * TT) + m0 + tx] = f2tf(t[tx][i]);
    }
}

__global__ __launch_bounds__(256) void ln_norm(const float* __restrict__ in1,
                                               const float* __restrict__ in2,
                                               const float* __restrict__ w,
                                               const float* __restrict__ bia,
                                               float* __restrict__ out) {
    size_t i = ((size_t)blockIdx.x * blockDim.x + threadIdx.x) * 4;
    if (i >= (size_t)BB * LN_N) return;
    int b = (int)(i / LN_N);
    size_t te = i % LN_N;
    float mean = g_stats[b * 2];
    float rstd = g_stats[b * 2 + 1];
    float4 a = *(const float4*)&in1[i];
    float4 c = *(const float4*)&in2[i];
    float4 ww = *(const float4*)&w[te];
    float4 bb = *(const float4*)&bia[te];
    float4 o;
    o.x = (a.x + c.x - mean) * rstd * ww.x + bb.x;
    o.y = (a.y + c.y - mean) * rstd * ww.y + bb.y;
    o.z = (a.z + c.z - mean) * rstd * ww.z + bb.z;
    o.w = (a.w + c.w - mean) * rstd * ww.w + bb.w;
    *(float4*)&out[i] = o;
}

// ---------------- launch -----------------------------------------------------
extern "C" void kernel_launch(void* const* d_in, const int* in_sizes, int n_in,
                              void* d_out, int out_size) {
    const float* x = (const float*)d_in[0];
    const float* q_w = (const float*)d_in[1];
    const float* k_w = (const float*)d_in[2];
    const float* v_w = (const float*)d_in[3];
    const float* fr_w = (const float*)d_in[4];
    const float* ff_w = (const float*)d_in[5];
    const float* ff_b = (const float*)d_in[6];
    const float* ln1_w = (const float*)d_in[7];
    const float* ln1_b = (const float*)d_in[8];
    const float* ln2_w = (const float*)d_in[9];
    const float* ln2_b = (const float*)d_in[10];
    float* out = (float*)d_out;

    float *p_wq, *p_wk, *p_q, *p_k, *p_v, *p_zf, *p_z1, *p_z2;
    uint32_t *p_wvhi, *p_wffhi, *p_frhi, *p_athi;
    cudaGetSymbolAddress((void**)&p_wq, g_wq);
    cudaGetSymbolAddress((void**)&p_wk, g_wk);
    cudaGetSymbolAddress((void**)&p_q, g_q);
    cudaGetSymbolAddress((void**)&p_k, g_k);
    cudaGetSymbolAddress((void**)&p_v, g_v);
    cudaGetSymbolAddress((void**)&p_zf, g_zf);
    cudaGetSymbolAddress((void**)&p_z1, g_z1);
    cudaGetSymbolAddress((void**)&p_z2, g_z2);
    cudaGetSymbolAddress((void**)&p_wvhi, g_wvhi);
    cudaGetSymbolAddress((void**)&p_wffhi, g_wffhi);
    cudaGetSymbolAddress((void**)&p_frhi, g_frhi);
    cudaGetSymbolAddress((void**)&p_athi, g_athi);

    const size_t SMP = 3 * T1_STAGE_U32 * sizeof(uint32_t);  // 52224 B
    const size_t SMA = sizeof(AttnSmem);                     // 88576 B
    cudaFuncSetAttribute(attn_fused, cudaFuncAttributeMaxDynamicSharedMemorySize, (int)SMA);
    cudaFuncSetAttribute(gemm_qkv, cudaFuncAttributeMaxDynamicSharedMemorySize, (int)SMP);
    cudaFuncSetAttribute(gemm_tf1<false>, cudaFuncAttributeMaxDynamicSharedMemorySize, (int)SMP);
    cudaFuncSetAttribute(gemm_tf1<true>, cudaFuncAttributeMaxDynamicSharedMemorySize, (int)SMP);

    // 1) merged weight repacks
    int repack_total = EE * EE + BB * EE * EE;
    repack_all<<<(repack_total + 255) / 256, 256>>>(q_w, k_w, v_w, ff_w, fr_w);

    // 2) transpose x (feeds V path of merged kernel)
    dim3 gtx(EE / 32, (BB * TT) / 32, 1);
    transpose_tf<<<gtx, 256>>>(x, p_athi, BB * TT, EE);

    // 3) merged QKV: z=0,1 exact fp32 Q/K; z=2 tensor-core V fills the tail
    dim3 gqkv(EE / 128, (BB * TT) / 128, 3);
    gemm_qkv<<<gqkv, 256, SMP>>>(x, p_wq, p_wk, p_q, p_k,
                                 p_athi, p_wvhi, p_v, BB * TT, EE, EE);

    // 4) fused attention (writes transposed tf32 athi directly, [B][E][T])
    dim3 gat(TT / 128, BB * HH, 1);
    attn_fused<<<gat, 256, SMA>>>();

    // 5) zf[b] = zm[b] @ fr[b] (1xTF32, batched; A = athi from attn epilogue)
    dim3 gfr(EE / 128, TT / 128, BB);
    gemm_tf1<false><<<gfr, 256, SMP>>>(p_athi, p_frhi, p_zf,
                                       TT, EE, EE, (long)TT * EE, (long)EE * EE,
                                       (long)TT * EE, nullptr);

    // 6) LN1 over x + zf -> z1, fused with transpose to athi [E][B*T]
    dim3 gred(64, BB, 1);
    ln_reduce<<<gred, 256>>>(x, p_zf);
    ln_finalize<<<BB, 64>>>();
    ln_norm_t<<<gtx, 256>>>(x, p_zf, ln1_w, ln1_b, p_z1, p_athi);

    // 7) FFN: z2 = relu(z1 @ ff_w^T + ff_b) (1xTF32; A = athi from LN1)
    dim3 gv(EE / 128, (BB * TT) / 128, 1);
    gemm_tf1<true><<<gv, 256, SMP>>>(p_athi, p_wffhi, p_z2,
                                     BB * TT, EE, EE, 0, 0, 0, ff_b);

    // 8) LN2 over z1 + z2 -> out
    ln_reduce<<<gred, 256>>>(p_z1, p_z2);
    ln_finalize<<<BB, 64>>>();
    size_t total = (size_t)BB * LN_N;
    ln_norm<<<(unsigned)((total / 4 + 255) / 256), 256>>>(p_z1, p_z2, ln2_w, ln2_b, out);
}

// round 15
// speedup vs baseline: 1.0793x; 1.0265x over previous
#include <cuda_runtime.h>
#include <math.h>
#include <stdint.h>

#define BB 4
#define TT 1024
#define EE 1024
#define HH 16
#define FFDIM 64
#define LN_N ((size_t)TT * EE)

// ---------------- scratch (static device globals; no allocation) -------------
__device__ float g_wq[EE * EE];
__device__ float g_wk[EE * EE];
__device__ float g_q[BB * TT * EE];
__device__ float g_k[BB * TT * EE];
__device__ float g_v[BB * TT * EE];
__device__ float g_zf[BB * TT * EE];
__device__ float g_z1[BB * TT * EE];
__device__ float g_z2[BB * TT * EE];
__device__ double g_part[BB * 64 * 2];
__device__ float g_stats[BB * 2];
__device__ uint32_t g_wvhi[EE * EE];
__device__ uint32_t g_wffhi[EE * EE];
__device__ uint32_t g_frhi[BB * EE * EE];
__device__ uint32_t g_athi[BB * TT * EE];  // transposed activation [K][M]

// ---------------- helpers ----------------------------------------------------
__device__ __forceinline__ uint32_t f2tf(float x) {
    uint32_t r;
    asm("cvt.rna.tf32.f32 %0, %1;" : "=r"(r) : "f"(x));
    return r;
}

__device__ __forceinline__ void mma8(float c[4], const uint32_t a[4], const uint32_t b[2]) {
    asm volatile(
        "mma.sync.aligned.m16n8k8.row.col.f32.tf32.tf32.f32 "
        "{%0,%1,%2,%3}, {%4,%5,%6,%7}, {%8,%9}, {%0,%1,%2,%3};\n"
        : "+f"(c[0]), "+f"(c[1]), "+f"(c[2]), "+f"(c[3])
        : "r"(a[0]), "r"(a[1]), "r"(a[2]), "r"(a[3]), "r"(b[0]), "r"(b[1]));
}

__device__ __forceinline__ uint32_t smem_u32(const void* p) {
    return (uint32_t)__cvta_generic_to_shared(p);
}
__device__ __forceinline__ void cpasync16(uint32_t dst, const void* src) {
    asm volatile("cp.async.ca.shared.global [%0], [%1], 16;\n" ::"r"(dst), "l"(src));
}

// ---------------- merged weight repacks --------------------------------------
__global__ void repack_all(const float* __restrict__ qw,
                           const float* __restrict__ kw,
                           const float* __restrict__ vw,
                           const float* __restrict__ ffw,
                           const float* __restrict__ frw) {
    int idx = blockIdx.x * blockDim.x + threadIdx.x;
    if (idx < EE * EE) {
        int e = idx / EE, n = idx % EE;
        int h = n >> 6, f = n & 63;
        int src = h * (EE * FFDIM) + e * FFDIM + f;
        g_wq[idx] = qw[src];
        g_wk[idx] = kw[src];
        g_wvhi[idx] = f2tf(vw[src]);
        g_wffhi[idx] = f2tf(ffw[n * EE + e]);
    }
    int idx2 = idx - EE * EE;
    if (idx2 >= 0 && idx2 < BB * EE * EE) g_frhi[idx2] = f2tf(frw[idx2]);
}

// ---------------- tiled transpose + tf32: [M][K] -> [K][M] -------------------
__global__ __launch_bounds__(256) void transpose_tf(
    const float* __restrict__ in, uint32_t* __restrict__ ohi, int M, int K) {
    __shared__ float t[32][33];
    int m0 = blockIdx.y * 32, k0 = blockIdx.x * 32;
    int tx = threadIdx.x & 31, ty = threadIdx.x >> 5;
#pragma unroll
    for (int i = ty; i < 32; i += 8) t[i][tx] = in[(size_t)(m0 + i) * K + k0 + tx];
    __syncthreads();
#pragma unroll
    for (int i = ty; i < 32; i += 8) {
        ohi[(size_t)(k0 + i) * M + m0 + tx] = f2tf(t[tx][i]);
    }
}

// ---------------- merged QKV GEMM (FROZEN fp32 chain for Q,K) ----------------
#define T1_STAGE_U32 (2 * 16 * 136)
__global__ __launch_bounds__(256, 2) void gemm_qkv(
    const float* __restrict__ A, const float* __restrict__ B0,
    const float* __restrict__ B1, float* __restrict__ C0, float* __restrict__ C1,
    const uint32_t* __restrict__ Ahi, const uint32_t* __restrict__ Bhi,
    float* __restrict__ CV, int M, int N, int K) {
    extern __shared__ uint32_t smp[];
    int m0 = blockIdx.y * 128, n0 = blockIdx.x * 128;
    int tid = threadIdx.x;

    if (blockIdx.z < 2) {
        const float* Bm = blockIdx.z ? B1 : B0;
        float* C = blockIdx.z ? C1 : C0;
        float* Asf = (float*)smp;             // [2][16][132]
        float* Bsf = Asf + 2 * 16 * 132;      // [2][16][128]
        int ty = tid >> 4, tx = tid & 15;
        float acc[8][8] = {};
        int ar = tid >> 2;
        int ac4 = (tid & 3) * 4;
        int bk = tid >> 5;
        int bc4 = (tid & 31) * 4;

        uint32_t bd0[2], bd1[2];
        bd0[0] = smem_u32(&Bsf[0 * 2048 + bk * 128 + bc4]);
        bd0[1] = smem_u32(&Bsf[1 * 2048 + bk * 128 + bc4]);
        bd1[0] = smem_u32(&Bsf[0 * 2048 + (bk + 8) * 128 + bc4]);
        bd1[1] = smem_u32(&Bsf[1 * 2048 + (bk + 8) * 128 + bc4]);

        cpasync16(bd0[0], &Bm[(size_t)bk * N + n0 + bc4]);
        cpasync16(bd1[0], &Bm[(size_t)(bk + 8) * N + n0 + bc4]);
        asm volatile("cp.async.commit_group;\n");
        float4 ra0 = *(const float4*)&A[(size_t)(m0 + ar) * K + ac4];
        float4 ra1 = *(const float4*)&A[(size_t)(m0 + ar + 64) * K + ac4];
        Asf[(ac4 + 0) * 132 + ar] = ra0.x; Asf[(ac4 + 1) * 132 + ar] = ra0.y;
        Asf[(ac4 + 2) * 132 + ar] = ra0.z; Asf[(ac4 + 3) * 132 + ar] = ra0.w;
        Asf[(ac4 + 0) * 132 + ar + 64] = ra1.x; Asf[(ac4 + 1) * 132 + ar + 64] = ra1.y;
        Asf[(ac4 + 2) * 132 + ar + 64] = ra1.z; Asf[(ac4 + 3) * 132 + ar + 64] = ra1.w;
        asm volatile("cp.async.wait_group 0;\n");
        __syncthreads();

        int nt = K / 16;
        for (int t = 0; t < nt; t++) {
            int s = t & 1;
            if (t + 1 < nt) {
                int k0 = (t + 1) * 16;
                cpasync16(bd0[s ^ 1], &Bm[(size_t)(k0 + bk) * N + n0 + bc4]);
                cpasync16(bd1[s ^ 1], &Bm[(size_t)(k0 + bk + 8) * N + n0 + bc4]);
                asm volatile("cp.async.commit_group;\n");
                ra0 = *(const float4*)&A[(size_t)(m0 + ar) * K + k0 + ac4];
                ra1 = *(const float4*)&A[(size_t)(m0 + ar + 64) * K + k0 + ac4];
            }
            const float* Asc = Asf + s * 2112;
            const float* Bsc = Bsf + s * 2048;
#pragma unroll
            for (int k = 0; k < 16; k++) {
                float a[8], b[8];
                *(float4*)&a[0] = *(const float4*)&Asc[k * 132 + ty * 8];
                *(float4*)&a[4] = *(const float4*)&Asc[k * 132 + ty * 8 + 4];
                *(float4*)&b[0] = *(const float4*)&Bsc[k * 128 + tx * 8];
                *(float4*)&b[4] = *(const float4*)&Bsc[k * 128 + tx * 8 + 4];
#pragma unroll
                for (int i = 0; i < 8; i++)
#pragma unroll
                    for (int j = 0; j < 8; j++) acc[i][j] += a[i] * b[j];
            }
            if (t + 1 < nt) {
                int s2 = s ^ 1;
                float* Asn = Asf + s2 * 2112;
                Asn[(ac4 + 0) * 132 + ar] = ra0.x; Asn[(ac4 + 1) * 132 + ar] = ra0.y;
                Asn[(ac4 + 2) * 132 + ar] = ra0.z; Asn[(ac4 + 3) * 132 + ar] = ra0.w;
                Asn[(ac4 + 0) * 132 + ar + 64] = ra1.x; Asn[(ac4 + 1) * 132 + ar + 64] = ra1.y;
                Asn[(ac4 + 2) * 132 + ar + 64] = ra1.z; Asn[(ac4 + 3) * 132 + ar + 64] = ra1.w;
                asm volatile("cp.async.wait_group 0;\n");
            }
            __syncthreads();
        }
#pragma unroll
        for (int i = 0; i < 8; i++) {
            int m = m0 + ty * 8 + i;
            *(float4*)&C[(size_t)m * N + n0 + tx * 8] = *(float4*)&acc[i][0];
            *(float4*)&C[(size_t)m * N + n0 + tx * 8 + 4] = *(float4*)&acc[i][4];
        }
    } else {
        // 1xTF32 tensor path (V projection)
        int lane = tid & 31, w = tid >> 5;
        int wm = w & 1, wn = w >> 1;
        int g = lane >> 2, tig = lane & 3;
        float acc[4][4][4] = {};
        int crow = tid >> 4;
        int col0 = (tid & 15) * 4;
        uint32_t sbase = smem_u32(smp);
        const uint32_t STAGE_B = T1_STAGE_U32 * 4;
        uint32_t offA = ((0 * 16 + crow) * 136 + col0) * 4;
        uint32_t offB = ((1 * 16 + crow) * 136 + col0) * 4;

        int nt = K / 16;
#pragma unroll
        for (int p = 0; p < 2; p++) {
            uint32_t dst = sbase + p * STAGE_B;
            const uint32_t* ga = &Ahi[(size_t)(p * 16 + crow) * M + m0 + col0];
            const uint32_t* gb = &Bhi[(size_t)(p * 16 + crow) * N + n0 + col0];
            cpasync16(dst + offA, ga);
            cpasync16(dst + offA + 256, ga + 64);
            cpasync16(dst + offB, gb);
            cpasync16(dst + offB + 256, gb + 64);
            asm volatile("cp.async.commit_group;\n");
        }
        asm volatile("cp.async.wait_group 1;\n");
        __syncthreads();

        int sl = 2, sc = 0;
        for (int t = 0; t < nt; t++) {
            if (t + 2 < nt) {
                uint32_t dst = sbase + sl * STAGE_B;
                const uint32_t* ga = &Ahi[(size_t)((t + 2) * 16 + crow) * M + m0 + col0];
                const uint32_t* gb = &Bhi[(size_t)((t + 2) * 16 + crow) * N + n0 + col0];
                cpasync16(dst + offA, ga);
                cpasync16(dst + offA + 256, ga + 64);
                cpasync16(dst + offB, gb);
                cpasync16(dst + offB + 256, gb + 64);
            }
            asm volatile("cp.async.commit_group;\n");
            const uint32_t* As = smp + sc * T1_STAGE_U32;
            const uint32_t* Bs = As + 16 * 136;
#pragma unroll
            for (int kk = 0; kk < 16; kk += 8) {
                uint32_t af[4][4];
#pragma unroll
                for (int mi = 0; mi < 4; mi++) {
                    int mb = wm * 64 + mi * 16 + g;
                    af[mi][0] = As[(kk + tig) * 136 + mb];
                    af[mi][1] = As[(kk + tig) * 136 + mb + 8];
                    af[mi][2] = As[(kk + tig + 4) * 136 + mb];
                    af[mi][3] = As[(kk + tig + 4) * 136 + mb + 8];
                }
#pragma unroll
                for (int ni = 0; ni < 4; ni++) {
                    int nb = wn * 32 + ni * 8 + g;
                    uint32_t bf[2];
                    bf[0] = Bs[(kk + tig) * 136 + nb];
                    bf[1] = Bs[(kk + tig + 4) * 136 + nb];
#pragma unroll
                    for (int mi = 0; mi < 4; mi++) mma8(acc[mi][ni], af[mi], bf);
                }
            }
            asm volatile("cp.async.wait_group 1;\n");
            __syncthreads();
            sl = (sl == 2) ? 0 : sl + 1;
            sc = (sc == 2) ? 0 : sc + 1;
        }
#pragma unroll
        for (int mi = 0; mi < 4; mi++) {
            int m = m0 + wm * 64 + mi * 16 + g;
#pragma unroll
            for (int ni = 0; ni < 4; ni++) {
                int n = n0 + wn * 32 + ni * 8 + tig * 2;
                *(float2*)&CV[(size_t)m * N + n] =
                    make_float2(acc[mi][ni][0], acc[mi][ni][1]);
                *(float2*)&CV[(size_t)(m + 8) * N + n] =
                    make_float2(acc[mi][ni][2], acc[mi][ni][3]);
            }
        }
    }
}

// ---------------- 1xTF32 tensor-core GEMM, 3-stage cp.async pipeline ---------
template <bool RELU>
__global__ __launch_bounds__(256, 2) void gemm_tf1(
    const uint32_t* __restrict__ Ahi, const uint32_t* __restrict__ Bhi,
    float* __restrict__ C, int M, int N, int K,
    long sA, long sB, long sC, const float* __restrict__ bias) {
    extern __shared__ uint32_t smp[];
    Ahi += (size_t)blockIdx.z * sA;
    Bhi += (size_t)blockIdx.z * sB;
    C += (size_t)blockIdx.z * sC;
    int m0 = blockIdx.y * 128, n0 = blockIdx.x * 128;
    int tid = threadIdx.x, lane = tid & 31, w = tid >> 5;
    int wm = w & 1, wn = w >> 1;
    int g = lane >> 2, tig = lane & 3;
    float acc[4][4][4] = {};

    int crow = tid >> 4;
    int col0 = (tid & 15) * 4;
    uint32_t sbase = smem_u32(smp);
    const uint32_t STAGE_B = T1_STAGE_U32 * 4;
    uint32_t offA = ((0 * 16 + crow) * 136 + col0) * 4;
    uint32_t offB = ((1 * 16 + crow) * 136 + col0) * 4;

    int nt = K / 16;
#pragma unroll
    for (int p = 0; p < 2; p++) {
        uint32_t dst = sbase + p * STAGE_B;
        const uint32_t* ga = &Ahi[(size_t)(p * 16 + crow) * M + m0 + col0];
        const uint32_t* gb = &Bhi[(size_t)(p * 16 + crow) * N + n0 + col0];
        cpasync16(dst + offA, ga);
        cpasync16(dst + offA + 256, ga + 64);
        cpasync16(dst + offB, gb);
        cpasync16(dst + offB + 256, gb + 64);
        asm volatile("cp.async.commit_group;\n");
    }
    asm volatile("cp.async.wait_group 1;\n");
    __syncthreads();

    int sl = 2, sc = 0;
    for (int t = 0; t < nt; t++) {
        if (t + 2 < nt) {
            uint32_t dst = sbase + sl * STAGE_B;
            const uint32_t* ga = &Ahi[(size_t)((t + 2) * 16 + crow) * M + m0 + col0];
            const uint32_t* gb = &Bhi[(size_t)((t + 2) * 16 + crow) * N + n0 + col0];
            cpasync16(dst + offA, ga);
            cpasync16(dst + offA + 256, ga + 64);
            cpasync16(dst + offB, gb);
            cpasync16(dst + offB + 256, gb + 64);
        }
        asm volatile("cp.async.commit_group;\n");
        const uint32_t* As = smp + sc * T1_STAGE_U32;
        const uint32_t* Bs = As + 16 * 136;
#pragma unroll
        for (int kk = 0; kk < 16; kk += 8) {
            uint32_t af[4][4];
#pragma unroll
            for (int mi = 0; mi < 4; mi++) {
                int mb = wm * 64 + mi * 16 + g;
                af[mi][0] = As[(kk + tig) * 136 + mb];
                af[mi][1] = As[(kk + tig) * 136 + mb + 8];
                af[mi][2] = As[(kk + tig + 4) * 136 + mb];
                af[mi][3] = As[(kk + tig + 4) * 136 + mb + 8];
            }
#pragma unroll
            for (int ni = 0; ni < 4; ni++) {
                int nb = wn * 32 + ni * 8 + g;
                uint32_t bf[2];
                bf[0] = Bs[(kk + tig) * 136 + nb];
                bf[1] = Bs[(kk + tig + 4) * 136 + nb];
#pragma unroll
                for (int mi = 0; mi < 4; mi++) mma8(acc[mi][ni], af[mi], bf);
            }
        }
        asm volatile("cp.async.wait_group 1;\n");
        __syncthreads();
        sl = (sl == 2) ? 0 : sl + 1;
        sc = (sc == 2) ? 0 : sc + 1;
    }
#pragma unroll
    for (int mi = 0; mi < 4; mi++) {
        int m = m0 + wm * 64 + mi * 16 + g;
#pragma unroll
        for (int ni = 0; ni < 4; ni++) {
            int n = n0 + wn * 32 + ni * 8 + tig * 2;
            float b0 = bias ? bias[n] : 0.0f;
            float b1 = bias ? bias[n + 1] : 0.0f;
            float v0 = acc[mi][ni][0] + b0, v1 = acc[mi][ni][1] + b1;
            float v2 = acc[mi][ni][2] + b0, v3 = acc[mi][ni][3] + b1;
            if (RELU) {
                v0 = fmaxf(v0, 0.0f); v1 = fmaxf(v1, 0.0f);
                v2 = fmaxf(v2, 0.0f); v3 = fmaxf(v3, 0.0f);
            }
            *(float2*)&C[(size_t)m * N + n] = make_float2(v0, v1);
            *(float2*)&C[(size_t)(m + 8) * N + n] = make_float2(v2, v3);
        }
    }
}

// ---------------- fused attention, BQ=128 BK=64, DESCENDING k order ----------
// Masked (upper-tri) tiles first -> running max saturates at ~1e12, so fully
// unmasked tiles hit the bit-exact -104 underflow skip on ALL rows and the
// whole exp/Ps/PV phase is skipped (dynamic per-tile flag). Scores chain,
// mask expression, reductions: FROZEN. PV 1xTF32; transposed tf32 epilogue.
struct __align__(16) AttnSmem {
    float qs[64][132];      // [f][q]
    uint32_t Ps[128][68];   // [q][k]; rows 0-63 alias ks[f][k]
    uint32_t vhi[64][72];   // [k][f] tf32
    float sm_m[128];
    float sm_l[128];
    float sm_sc[128];
    int active[2];          // per-tile-parity activity flags
};

__global__ __launch_bounds__(256, 2) void attn_fused() {
    extern __shared__ char smraw[];
    AttnSmem* S = (AttnSmem*)smraw;
    float(*ks)[68] = (float(*)[68])S->Ps;
    int bh = blockIdx.y;
    int b = bh / HH, h = bh % HH;
    int q0 = blockIdx.x * 128;
    const float* qp = g_q + (size_t)b * TT * EE + h * FFDIM;
    const float* kp = g_k + (size_t)b * TT * EE + h * FFDIM;
    const float* vp = g_v + (size_t)b * TT * EE + h * FFDIM;

    int tid = threadIdx.x;
    int ty = tid >> 4, tx = tid & 15;
    int lane = tid & 31, w = tid >> 5;
    int wm = w >> 1, wn = w & 1;
    int g = lane >> 2, tig = lane & 3;
    int ar = tid >> 2;            // 0..63
    int ac4 = (tid & 3) * 4;
    int vr = tid >> 2;
    int vc = (tid & 3) * 16;

    // load Q tile (once)
#pragma unroll
    for (int c0 = 0; c0 < 64; c0 += 16) {
#pragma unroll
        for (int ri = 0; ri < 2; ri++) {
            int r = ar + ri * 64;
            const float4 va = *(const float4*)&qp[(size_t)(q0 + r) * EE + c0 + ac4];
            S->qs[c0 + ac4 + 0][r] = va.x;
            S->qs[c0 + ac4 + 1][r] = va.y;
            S->qs[c0 + ac4 + 2][r] = va.z;
            S->qs[c0 + ac4 + 3][r] = va.w;
        }
    }
    if (tid < 128) {
        S->sm_m[tid] = -INFINITY;
        S->sm_l[tid] = 0.0f;
    }
    if (tid < 2) S->active[tid] = 0;
    // prologue: last tile (kt=15) K,V into smem
    {
        int k0 = TT - 64;
#pragma unroll
        for (int c = 0; c < 4; c++) {
            const float4 vb = *(const float4*)&kp[(size_t)(k0 + ar) * EE + c * 16 + ac4];
            ks[c * 16 + ac4 + 0][ar] = vb.x;
            ks[c * 16 + ac4 + 1][ar] = vb.y;
            ks[c * 16 + ac4 + 2][ar] = vb.z;
            ks[c * 16 + ac4 + 3][ar] = vb.w;
        }
#pragma unroll
        for (int j = 0; j < 4; j++) {
            const float4 v = *(const float4*)&vp[(size_t)(k0 + vr) * EE + vc + j * 4];
            uint4 t;
            t.x = f2tf(v.x); t.y = f2tf(v.y); t.z = f2tf(v.z); t.w = f2tf(v.w);
            *(uint4*)&S->vhi[vr][vc + j * 4] = t;
        }
    }
    float acc[2][4][4] = {};
    __syncthreads();

    for (int kt = TT / 64 - 1; kt >= 0; kt--) {
        int k0 = kt * 64;
        int par = kt & 1;
        bool more = (kt > 0);
        float4 kr[4], vrg[4];
        if (more) {  // prefetch next (lower) K/V tile into regs
#pragma unroll
            for (int c = 0; c < 4; c++)
                kr[c] = *(const float4*)&kp[(size_t)(k0 - 64 + ar) * EE + c * 16 + ac4];
#pragma unroll
            for (int j = 0; j < 4; j++)
                vrg[j] = *(const float4*)&vp[(size_t)(k0 - 64 + vr) * EE + vc + j * 4];
        }

        // scores: 8 rows x 4 cols, ascending f (FROZEN fp32 chain)
        float s[8][4] = {};
#pragma unroll
        for (int f = 0; f < 64; f++) {
            float a[8], bv[4];
            *(float4*)&a[0] = *(const float4*)&S->qs[f][ty * 8];
            *(float4*)&a[4] = *(const float4*)&S->qs[f][ty * 8 + 4];
            *(float4*)&bv[0] = *(const float4*)&ks[f][tx * 4];
#pragma unroll
            for (int i = 0; i < 8; i++)
#pragma unroll
                for (int j = 0; j < 4; j++) s[i][j] += a[i] * bv[j];
        }
        // mask + scale (identical expression)
#pragma unroll
        for (int i = 0; i < 8; i++) {
            int qg = q0 + ty * 8 + i;
#pragma unroll
            for (int j = 0; j < 4; j++) {
                int kg = k0 + tx * 4 + j;
                float m = (kg > qg) ? (1.0f - 1.0e9f) : 1.0f;
                s[i][j] = s[i][j] * m * 0.125f;
            }
        }
        // tile row max
        float tm[8];
#pragma unroll
        for (int i = 0; i < 8; i++) {
            float v = fmaxf(fmaxf(s[i][0], s[i][1]), fmaxf(s[i][2], s[i][3]));
#pragma unroll
            for (int o = 8; o > 0; o >>= 1) v = fmaxf(v, __shfl_xor_sync(0xffffffffu, v, o));
            tm[i] = v;
        }
        if (tx == 0) {
            int rowact = 0;
#pragma unroll
            for (int i = 0; i < 8; i++) {
                int row = ty * 8 + i;
                float mo = S->sm_m[row];
                float mn = fmaxf(mo, tm[i]);
                S->sm_sc[row] = __expf(mo - mn);
                S->sm_m[row] = mn;
                if (tm[i] - mn > -104.0f) rowact = 1;
            }
            if (rowact) atomicOr(&S->active[par], 1);
        }
        __syncthreads();  // A: publish sm_m/sc/active; fence ks reads

        int act = S->active[par];
        if (tid == 0) S->active[par ^ 1] = 0;  // reset other parity for next tile

        if (act) {
            // P = exp(s - m_new); per-row bit-exact underflow skip
            unsigned hm = (lane & 16) ? 0xffff0000u : 0x0000ffffu;
#pragma unroll
            for (int i = 0; i < 8; i++) {
                int row = ty * 8 + i;
                float mn = S->sm_m[row];
                if (tm[i] - mn > -104.0f) {
                    float p0 = __expf(s[i][0] - mn);
                    float p1 = __expf(s[i][1] - mn);
                    float p2 = __expf(s[i][2] - mn);
                    float p3 = __expf(s[i][3] - mn);
                    float rs = p0 + p1 + p2 + p3;
                    *(uint4*)&S->Ps[row][tx * 4] =
                        make_uint4(f2tf(p0), f2tf(p1), f2tf(p2), f2tf(p3));
#pragma unroll
                    for (int o = 8; o > 0; o >>= 1) rs += __shfl_xor_sync(hm, rs, o);
                    if (tx == 0) S->sm_l[row] = S->sm_l[row] * S->sm_sc[row] + rs;
                } else {
                    *(uint4*)&S->Ps[row][tx * 4] = make_uint4(0, 0, 0, 0);
                }
            }
            __syncthreads();  // B: Ps visible

            // rescale O accumulators, then PV mma (1xTF32)
#pragma unroll
            for (int mi = 0; mi < 2; mi++) {
                int row = wm * 32 + mi * 16 + g;
                float s0 = S->sm_sc[row], s1 = S->sm_sc[row + 8];
#pragma unroll
                for (int ni = 0; ni < 4; ni++) {
                    acc[mi][ni][0] *= s0; acc[mi][ni][1] *= s0;
                    acc[mi][ni][2] *= s1; acc[mi][ni][3] *= s1;
                }
            }
#pragma unroll
            for (int kk = 0; kk < 64; kk += 8) {
                uint32_t af[2][4];
#pragma unroll
                for (int mi = 0; mi < 2; mi++) {
                    int mb = wm * 32 + mi * 16 + g;
                    af[mi][0] = S->Ps[mb][kk + tig];
                    af[mi][1] = S->Ps[mb + 8][kk + tig];
                    af[mi][2] = S->Ps[mb][kk + tig + 4];
                    af[mi][3] = S->Ps[mb + 8][kk + tig + 4];
                }
#pragma unroll
                for (int ni = 0; ni < 4; ni++) {
                    int nb = wn * 32 + ni * 8 + g;
                    uint32_t bf[2];
                    bf[0] = S->vhi[kk + tig][nb];
                    bf[1] = S->vhi[kk + tig + 4][nb];
#pragma unroll
                    for (int mi = 0; mi < 2; mi++) mma8(acc[mi][ni], af[mi], bf);
                }
            }
            __syncthreads();  // C: fence Ps/vhi reads before next-tile stores
        }
        // (skip path: sc==1 for all rows, rs==0 -> acc and sm_l unchanged;
        //  ks/vhi safe to overwrite after sync A since PV was skipped)

        if (more) {  // store prefetched K/V into smem
#pragma unroll
            for (int c = 0; c < 4; c++) {
                ks[c * 16 + ac4 + 0][ar] = kr[c].x;
                ks[c * 16 + ac4 + 1][ar] = kr[c].y;
                ks[c * 16 + ac4 + 2][ar] = kr[c].z;
                ks[c * 16 + ac4 + 3][ar] = kr[c].w;
            }
#pragma unroll
            for (int j = 0; j < 4; j++) {
                uint4 t;
                t.x = f2tf(vrg[j].x); t.y = f2tf(vrg[j].y);
                t.z = f2tf(vrg[j].z); t.w = f2tf(vrg[j].w);
                *(uint4*)&S->vhi[vr][vc + j * 4] = t;
            }
        }
        __syncthreads();  // D: KV stores visible (and active-flag reset fenced)
    }
    // epilogue: O /= l, write transposed tf32 directly into g_athi [B][E][T]
    {
        size_t obase = (size_t)b * EE * TT + (size_t)h * 64 * TT;
#pragma unroll
        for (int mi = 0; mi < 2; mi++) {
            int row = wm * 32 + mi * 16 + g;
            float i0 = 1.0f / S->sm_l[row];
            float i1 = 1.0f / S->sm_l[row + 8];
            int m = q0 + row;
#pragma unroll
            for (int ni = 0; ni < 4; ni++) {
                int n = wn * 32 + ni * 8 + tig * 2;
                g_athi[obase + (size_t)n * TT + m] = f2tf(acc[mi][ni][0] * i0);
                g_athi[obase + (size_t)(n + 1) * TT + m] = f2tf(acc[mi][ni][1] * i0);
                g_athi[obase + (size_t)n * TT + m + 8] = f2tf(acc[mi][ni][2] * i1);
                g_athi[obase + (size_t)(n + 1) * TT + m + 8] = f2tf(acc[mi][ni][3] * i1);
            }
        }
    }
}

// ---------------- LayerNorm over whole [T,E] plane per batch -----------------
__global__ __launch_bounds__(256) void ln_reduce(const float* __restrict__ in1,
                                                 const float* __restrict__ in2) {
    int b = blockIdx.y;
    const float* p1 = in1 + (size_t)b * LN_N;
    const float* p2 = in2 + (size_t)b * LN_N;
    const int chunk = (int)(LN_N / 64);
    size_t base = (size_t)blockIdx.x * chunk;
    double s = 0.0, sq = 0.0;
    for (int i = threadIdx.x * 4; i < chunk; i += 256 * 4) {
        float4 a = *(const float4*)&p1[base + i];
        float4 c = *(const float4*)&p2[base + i];
        float x0 = a.x + c.x, x1 = a.y + c.y, x2 = a.z + c.z, x3 = a.w + c.w;
        s += (double)x0 + (double)x1 + (double)x2 + (double)x3;
        sq += (double)x0 * x0 + (double)x1 * x1 + (double)x2 * x2 + (double)x3 * x3;
    }
    __shared__ double sh[256], shq[256];
    int tid = threadIdx.x;
    sh[tid] = s;
    shq[tid] = sq;
    __syncthreads();
    for (int o = 128; o > 0; o >>= 1) {
        if (tid < o) {
            sh[tid] += sh[tid + o];
            shq[tid] += shq[tid + o];
        }
        __syncthreads();
    }
    if (tid == 0) {
        g_part[(b * 64 + blockIdx.x) * 2] = sh[0];
        g_part[(b * 64 + blockIdx.x) * 2 + 1] = shq[0];
    }
}

__global__ void ln_finalize() {
    int b = blockIdx.x;
    int tid = threadIdx.x;
    __shared__ double sh[64], shq[64];
    sh[tid] = g_part[(b * 64 + tid) * 2];
    shq[tid] = g_part[(b * 64 + tid) * 2 + 1];
    __syncthreads();
    for (int o = 32; o > 0; o >>= 1) {
        if (tid < o) {
            sh[tid] += sh[tid + o];
            shq[tid] += shq[tid + o];
        }
        __syncthreads();
    }
    if (tid == 0) {
        double n = (double)LN_N;
        double mean = sh[0] / n;
        double var = shq[0] / n - mean * mean;
        g_stats[b * 2] = (float)mean;
        g_stats[b * 2 + 1] = (float)(1.0 / sqrt(var + 1e-5));
    }
}

// LN1 fused with transpose: writes z1 AND transposed tf32 athi
__global__ __launch_bounds__(256) void ln_norm_t(
    const float* __restrict__ in1, const float* __restrict__ in2,
    const float* __restrict__ w, const float* __restrict__ bia,
    float* __restrict__ out, uint32_t* __restrict__ ohi) {
    __shared__ float t[32][33];
    int m0 = blockIdx.y * 32, k0 = blockIdx.x * 32;
    int tx = threadIdx.x & 31, ty = threadIdx.x >> 5;
    int b = m0 / TT;
    float mean = g_stats[b * 2];
    float rstd = g_stats[b * 2 + 1];
#pragma unroll
    for (int i = ty; i < 32; i += 8) {
        int row = m0 + i;
        size_t idx = (size_t)row * EE + k0 + tx;
        size_t te = (size_t)(row % TT) * EE + k0 + tx;
        float v = (in1[idx] + in2[idx] - mean) * rstd * w[te] + bia[te];
        out[idx] = v;
        t[i][tx] = v;
    }
    __syncthreads();
#pragma unroll
    for (int i = ty; i < 32; i += 8) {
        ohi[(size_t)(k0 + i) * (BB * TT) + m0 + tx] = f2tf(t[tx][i]);
    }
}

__global__ __launch_bounds__(256) void ln_norm(const float* __restrict__ in1,
                                               const float* __restrict__ in2,
                                               const float* __restrict__ w,
                                               const float* __restrict__ bia,
                                               float* __restrict__ out) {
    size_t i = ((size_t)blockIdx.x * blockDim.x + threadIdx.x) * 4;
    if (i >= (size_t)BB * LN_N) return;
    int b = (int)(i / LN_N);
    size_t te = i % LN_N;
    float mean = g_stats[b * 2];
    float rstd = g_stats[b * 2 + 1];
    float4 a = *(const float4*)&in1[i];
    float4 c = *(const float4*)&in2[i];
    float4 ww = *(const float4*)&w[te];
    float4 bb = *(const float4*)&bia[te];
    float4 o;
    o.x = (a.x + c.x - mean) * rstd * ww.x + bb.x;
    o.y = (a.y + c.y - mean) * rstd * ww.y + bb.y;
    o.z = (a.z + c.z - mean) * rstd * ww.z + bb.z;
    o.w = (a.w + c.w - mean) * rstd * ww.w + bb.w;
    *(float4*)&out[i] = o;
}

// ---------------- launch -----------------------------------------------------
extern "C" void kernel_launch(void* const* d_in, const int* in_sizes, int n_in,
                              void* d_out, int out_size) {
    const float* x = (const float*)d_in[0];
    const float* q_w = (const float*)d_in[1];
    const float* k_w = (const float*)d_in[2];
    const float* v_w = (const float*)d_in[3];
    const float* fr_w = (const float*)d_in[4];
    const float* ff_w = (const float*)d_in[5];
    const float* ff_b = (const float*)d_in[6];
    const float* ln1_w = (const float*)d_in[7];
    const float* ln1_b = (const float*)d_in[8];
    const float* ln2_w = (const float*)d_in[9];
    const float* ln2_b = (const float*)d_in[10];
    float* out = (float*)d_out;

    float *p_wq, *p_wk, *p_q, *p_k, *p_v, *p_zf, *p_z1, *p_z2;
    uint32_t *p_wvhi, *p_wffhi, *p_frhi, *p_athi;
    cudaGetSymbolAddress((void**)&p_wq, g_wq);
    cudaGetSymbolAddress((void**)&p_wk, g_wk);
    cudaGetSymbolAddress((void**)&p_q, g_q);
    cudaGetSymbolAddress((void**)&p_k, g_k);
    cudaGetSymbolAddress((void**)&p_v, g_v);
    cudaGetSymbolAddress((void**)&p_zf, g_zf);
    cudaGetSymbolAddress((void**)&p_z1, g_z1);
    cudaGetSymbolAddress((void**)&p_z2, g_z2);
    cudaGetSymbolAddress((void**)&p_wvhi, g_wvhi);
    cudaGetSymbolAddress((void**)&p_wffhi, g_wffhi);
    cudaGetSymbolAddress((void**)&p_frhi, g_frhi);
    cudaGetSymbolAddress((void**)&p_athi, g_athi);

    const size_t SMP = 3 * T1_STAGE_U32 * sizeof(uint32_t);
    const size_t SMA = sizeof(AttnSmem);
    cudaFuncSetAttribute(attn_fused, cudaFuncAttributeMaxDynamicSharedMemorySize, (int)SMA);
    cudaFuncSetAttribute(gemm_qkv, cudaFuncAttributeMaxDynamicSharedMemorySize, (int)SMP);
    cudaFuncSetAttribute(gemm_tf1<false>, cudaFuncAttributeMaxDynamicSharedMemorySize, (int)SMP);
    cudaFuncSetAttribute(gemm_tf1<true>, cudaFuncAttributeMaxDynamicSharedMemorySize, (int)SMP);

    // 1) merged weight repacks
    int repack_total = EE * EE + BB * EE * EE;
    repack_all<<<(repack_total + 255) / 256, 256>>>(q_w, k_w, v_w, ff_w, fr_w);

    // 2) transpose x (feeds V path of merged kernel)
    dim3 gtx(EE / 32, (BB * TT) / 32, 1);
    transpose_tf<<<gtx, 256>>>(x, p_athi, BB * TT, EE);

    // 3) merged QKV
    dim3 gqkv(EE / 128, (BB * TT) / 128, 3);
    gemm_qkv<<<gqkv, 256, SMP>>>(x, p_wq, p_wk, p_q, p_k,
                                 p_athi, p_wvhi, p_v, BB * TT, EE, EE);

    // 4) fused attention (descending k, tile-skip; writes transposed athi)
    dim3 gat(TT / 128, BB * HH, 1);
    attn_fused<<<gat, 256, SMA>>>();

    // 5) zf[b] = zm[b] @ fr[b]
    dim3 gfr(EE / 128, TT / 128, BB);
    gemm_tf1<false><<<gfr, 256, SMP>>>(p_athi, p_frhi, p_zf,
                                       TT, EE, EE, (long)TT * EE, (long)EE * EE,
                                       (long)TT * EE, nullptr);

    // 6) LN1 over x + zf -> z1, fused with transpose to athi
    dim3 gred(64, BB, 1);
    ln_reduce<<<gred, 256>>>(x, p_zf);
    ln_finalize<<<BB, 64>>>();
    ln_norm_t<<<gtx, 256>>>(x, p_zf, ln1_w, ln1_b, p_z1, p_athi);

    // 7) FFN: z2 = relu(z1 @ ff_w^T + ff_b)
    dim3 gv(EE / 128, (BB * TT) / 128, 1);
    gemm_tf1<true><<<gv, 256, SMP>>>(p_athi, p_wffhi, p_z2,
                                     BB * TT, EE, EE, 0, 0, 0, ff_b);

    // 8) LN2 over z1 + z2 -> out
    ln_reduce<<<gred, 256>>>(p_z1, p_z2);
    ln_finalize<<<BB, 64>>>();
    size_t total = (size_t)BB * LN_N;
    ln_norm<<<(unsigned)((total / 4 + 255) / 256), 256>>>(p_z1, p_z2, ln2_w, ln2_b, out);
}

// round 16
// speedup vs baseline: 1.1113x; 1.0297x over previous
#include <cuda_runtime.h>
#include <math.h>
#include <stdint.h>

#define BB 4
#define TT 1024
#define EE 1024
#define HH 16
#define FFDIM 64
#define LN_N ((size_t)TT * EE)

// ---------------- scratch (static device globals; no allocation) -------------
__device__ float g_wq[EE * EE];
__device__ float g_wk[EE * EE];
__device__ float g_q[BB * TT * EE];
__device__ float g_k[BB * TT * EE];
__device__ float g_v[BB * TT * EE];
__device__ float g_zf[BB * TT * EE];
__device__ float g_z1[BB * TT * EE];
__device__ float g_z2[BB * TT * EE];
__device__ double g_part[BB * 64 * 2];
__device__ float g_stats[BB * 2];
__device__ uint32_t g_wvhi[EE * EE];
__device__ uint32_t g_wffhi[EE * EE];
__device__ uint32_t g_frhi[BB * EE * EE];
__device__ uint32_t g_athi[BB * TT * EE];  // transposed activation [K][M]
__device__ float g_kmax[BB * HH * 16];     // per (bh, k-tile) max key L2 norm
__device__ float g_qmax[BB * HH * 8];      // per (bh, q-block) max query L2 norm

// ---------------- helpers ----------------------------------------------------
__device__ __forceinline__ uint32_t f2tf(float x) {
    uint32_t r;
    asm("cvt.rna.tf32.f32 %0, %1;" : "=r"(r) : "f"(x));
    return r;
}

__device__ __forceinline__ void mma8(float c[4], const uint32_t a[4], const uint32_t b[2]) {
    asm volatile(
        "mma.sync.aligned.m16n8k8.row.col.f32.tf32.tf32.f32 "
        "{%0,%1,%2,%3}, {%4,%5,%6,%7}, {%8,%9}, {%0,%1,%2,%3};\n"
        : "+f"(c[0]), "+f"(c[1]), "+f"(c[2]), "+f"(c[3])
        : "r"(a[0]), "r"(a[1]), "r"(a[2]), "r"(a[3]), "r"(b[0]), "r"(b[1]));
}

__device__ __forceinline__ uint32_t smem_u32(const void* p) {
    return (uint32_t)__cvta_generic_to_shared(p);
}
__device__ __forceinline__ void cpasync16(uint32_t dst, const void* src) {
    asm volatile("cp.async.ca.shared.global [%0], [%1], 16;\n" ::"r"(dst), "l"(src));
}

// ---------------- merged weight repacks --------------------------------------
__global__ void repack_all(const float* __restrict__ qw,
                           const float* __restrict__ kw,
                           const float* __restrict__ vw,
                           const float* __restrict__ ffw,
                           const float* __restrict__ frw) {
    int idx = blockIdx.x * blockDim.x + threadIdx.x;
    if (idx < EE * EE) {
        int e = idx / EE, n = idx % EE;
        int h = n >> 6, f = n & 63;
        int src = h * (EE * FFDIM) + e * FFDIM + f;
        g_wq[idx] = qw[src];
        g_wk[idx] = kw[src];
        g_wvhi[idx] = f2tf(vw[src]);
        g_wffhi[idx] = f2tf(ffw[n * EE + e]);
    }
    int idx2 = idx - EE * EE;
    if (idx2 >= 0 && idx2 < BB * EE * EE) g_frhi[idx2] = f2tf(frw[idx2]);
}

// ---------------- Q/K row-norm maxima (for provable tile skip) ---------------
// grid (24, B*H): x<16 -> k-tile kt=x (max over 64 key norms);
//                 x>=16 -> q-block qb=x-16 (max over 128 query norms)
__global__ __launch_bounds__(128) void qk_norms() {
    int bh = blockIdx.y;
    int b = bh / HH, h = bh % HH;
    __shared__ float red[128];
    int tid = threadIdx.x;
    float nrm = 0.0f;
    if (blockIdx.x < 16) {
        if (tid < 64) {
            const float* p = g_k + ((size_t)b * TT + blockIdx.x * 64 + tid) * EE + h * 64;
            float s = 0.0f;
#pragma unroll
            for (int f = 0; f < 64; f += 4) {
                float4 v = *(const float4*)&p[f];
                s += v.x * v.x + v.y * v.y + v.z * v.z + v.w * v.w;
            }
            nrm = sqrtf(s);
        }
    } else {
        const float* p = g_q + ((size_t)b * TT + (blockIdx.x - 16) * 128 + tid) * EE + h * 64;
        float s = 0.0f;
#pragma unroll
        for (int f = 0; f < 64; f += 4) {
            float4 v = *(const float4*)&p[f];
            s += v.x * v.x + v.y * v.y + v.z * v.z + v.w * v.w;
        }
        nrm = sqrtf(s);
    }
    red[tid] = nrm;
    __syncthreads();
    for (int o = 64; o > 0; o >>= 1) {
        if (tid < o) red[tid] = fmaxf(red[tid], red[tid + o]);
        __syncthreads();
    }
    if (tid == 0) {
        if (blockIdx.x < 16) g_kmax[bh * 16 + blockIdx.x] = red[0];
        else g_qmax[bh * 8 + (blockIdx.x - 16)] = red[0];
    }
}

// ---------------- merged QKV GEMM (FROZEN fp32 chain for Q,K) ----------------
#define T1_STAGE_U32 (2 * 16 * 136)
__global__ __launch_bounds__(256, 2) void gemm_qkv(
    const float* __restrict__ A, const float* __restrict__ B0,
    const float* __restrict__ B1, float* __restrict__ C0, float* __restrict__ C1,
    const uint32_t* __restrict__ Ahi, const uint32_t* __restrict__ Bhi,
    float* __restrict__ CV, int M, int N, int K) {
    extern __shared__ uint32_t smp[];
    int m0 = blockIdx.y * 128, n0 = blockIdx.x * 128;
    int tid = threadIdx.x;

    if (blockIdx.z < 2) {
        const float* Bm = blockIdx.z ? B1 : B0;
        float* C = blockIdx.z ? C1 : C0;
        float* Asf = (float*)smp;
        float* Bsf = Asf + 2 * 16 * 132;
        int ty = tid >> 4, tx = tid & 15;
        float acc[8][8] = {};
        int ar = tid >> 2;
        int ac4 = (tid & 3) * 4;
        int bk = tid >> 5;
        int bc4 = (tid & 31) * 4;

        uint32_t bd0[2], bd1[2];
        bd0[0] = smem_u32(&Bsf[0 * 2048 + bk * 128 + bc4]);
        bd0[1] = smem_u32(&Bsf[1 * 2048 + bk * 128 + bc4]);
        bd1[0] = smem_u32(&Bsf[0 * 2048 + (bk + 8) * 128 + bc4]);
        bd1[1] = smem_u32(&Bsf[1 * 2048 + (bk + 8) * 128 + bc4]);

        cpasync16(bd0[0], &Bm[(size_t)bk * N + n0 + bc4]);
        cpasync16(bd1[0], &Bm[(size_t)(bk + 8) * N + n0 + bc4]);
        asm volatile("cp.async.commit_group;\n");
        float4 ra0 = *(const float4*)&A[(size_t)(m0 + ar) * K + ac4];
        float4 ra1 = *(const float4*)&A[(size_t)(m0 + ar + 64) * K + ac4];
        Asf[(ac4 + 0) * 132 + ar] = ra0.x; Asf[(ac4 + 1) * 132 + ar] = ra0.y;
        Asf[(ac4 + 2) * 132 + ar] = ra0.z; Asf[(ac4 + 3) * 132 + ar] = ra0.w;
        Asf[(ac4 + 0) * 132 + ar + 64] = ra1.x; Asf[(ac4 + 1) * 132 + ar + 64] = ra1.y;
        Asf[(ac4 + 2) * 132 + ar + 64] = ra1.z; Asf[(ac4 + 3) * 132 + ar + 64] = ra1.w;
        asm volatile("cp.async.wait_group 0;\n");
        __syncthreads();

        int nt = K / 16;
        for (int t = 0; t < nt; t++) {
            int s = t & 1;
            if (t + 1 < nt) {
                int k0 = (t + 1) * 16;
                cpasync16(bd0[s ^ 1], &Bm[(size_t)(k0 + bk) * N + n0 + bc4]);
                cpasync16(bd1[s ^ 1], &Bm[(size_t)(k0 + bk + 8) * N + n0 + bc4]);
                asm volatile("cp.async.commit_group;\n");
                ra0 = *(const float4*)&A[(size_t)(m0 + ar) * K + k0 + ac4];
                ra1 = *(const float4*)&A[(size_t)(m0 + ar + 64) * K + k0 + ac4];
            }
            const float* Asc = Asf + s * 2112;
            const float* Bsc = Bsf + s * 2048;
#pragma unroll
            for (int k = 0; k < 16; k++) {
                float a[8], b[8];
                *(float4*)&a[0] = *(const float4*)&Asc[k * 132 + ty * 8];
                *(float4*)&a[4] = *(const float4*)&Asc[k * 132 + ty * 8 + 4];
                *(float4*)&b[0] = *(const float4*)&Bsc[k * 128 + tx * 8];
                *(float4*)&b[4] = *(const float4*)&Bsc[k * 128 + tx * 8 + 4];
#pragma unroll
                for (int i = 0; i < 8; i++)
#pragma unroll
                    for (int j = 0; j < 8; j++) acc[i][j] += a[i] * b[j];
            }
            if (t + 1 < nt) {
                int s2 = s ^ 1;
                float* Asn = Asf + s2 * 2112;
                Asn[(ac4 + 0) * 132 + ar] = ra0.x; Asn[(ac4 + 1) * 132 + ar] = ra0.y;
                Asn[(ac4 + 2) * 132 + ar] = ra0.z; Asn[(ac4 + 3) * 132 + ar] = ra0.w;
                Asn[(ac4 + 0) * 132 + ar + 64] = ra1.x; Asn[(ac4 + 1) * 132 + ar + 64] = ra1.y;
                Asn[(ac4 + 2) * 132 + ar + 64] = ra1.z; Asn[(ac4 + 3) * 132 + ar + 64] = ra1.w;
                asm volatile("cp.async.wait_group 0;\n");
            }
            __syncthreads();
        }
#pragma unroll
        for (int i = 0; i < 8; i++) {
            int m = m0 + ty * 8 + i;
            *(float4*)&C[(size_t)m * N + n0 + tx * 8] = *(float4*)&acc[i][0];
            *(float4*)&C[(size_t)m * N + n0 + tx * 8 + 4] = *(float4*)&acc[i][4];
        }
    } else {
        // 1xTF32 tensor path (V projection)
        int lane = tid & 31, w = tid >> 5;
        int wm = w & 1, wn = w >> 1;
        int g = lane >> 2, tig = lane & 3;
        float acc[4][4][4] = {};
        int crow = tid >> 4;
        int col0 = (tid & 15) * 4;
        uint32_t sbase = smem_u32(smp);
        const uint32_t STAGE_B = T1_STAGE_U32 * 4;
        uint32_t offA = ((0 * 16 + crow) * 136 + col0) * 4;
        uint32_t offB = ((1 * 16 + crow) * 136 + col0) * 4;

        int nt = K / 16;
#pragma unroll
        for (int p = 0; p < 2; p++) {
            uint32_t dst = sbase + p * STAGE_B;
            const uint32_t* ga = &Ahi[(size_t)(p * 16 + crow) * M + m0 + col0];
            const uint32_t* gb = &Bhi[(size_t)(p * 16 + crow) * N + n0 + col0];
            cpasync16(dst + offA, ga);
            cpasync16(dst + offA + 256, ga + 64);
            cpasync16(dst + offB, gb);
            cpasync16(dst + offB + 256, gb + 64);
            asm volatile("cp.async.commit_group;\n");
        }
        asm volatile("cp.async.wait_group 1;\n");
        __syncthreads();

        int sl = 2, sc = 0;
        for (int t = 0; t < nt; t++) {
            if (t + 2 < nt) {
                uint32_t dst = sbase + sl * STAGE_B;
                const uint32_t* ga = &Ahi[(size_t)((t + 2) * 16 + crow) * M + m0 + col0];
                const uint32_t* gb = &Bhi[(size_t)((t + 2) * 16 + crow) * N + n0 + col0];
                cpasync16(dst + offA, ga);
                cpasync16(dst + offA + 256, ga + 64);
                cpasync16(dst + offB, gb);
                cpasync16(dst + offB + 256, gb + 64);
            }
            asm volatile("cp.async.commit_group;\n");
            const uint32_t* As = smp + sc * T1_STAGE_U32;
            const uint32_t* Bs = As + 16 * 136;
#pragma unroll
            for (int kk = 0; kk < 16; kk += 8) {
                uint32_t af[4][4];
#pragma unroll
                for (int mi = 0; mi < 4; mi++) {
                    int mb = wm * 64 + mi * 16 + g;
                    af[mi][0] = As[(kk + tig) * 136 + mb];
                    af[mi][1] = As[(kk + tig) * 136 + mb + 8];
                    af[mi][2] = As[(kk + tig + 4) * 136 + mb];
                    af[mi][3] = As[(kk + tig + 4) * 136 + mb + 8];
                }
#pragma unroll
                for (int ni = 0; ni < 4; ni++) {
                    int nb = wn * 32 + ni * 8 + g;
                    uint32_t bf[2];
                    bf[0] = Bs[(kk + tig) * 136 + nb];
                    bf[1] = Bs[(kk + tig + 4) * 136 + nb];
#pragma unroll
                    for (int mi = 0; mi < 4; mi++) mma8(acc[mi][ni], af[mi], bf);
                }
            }
            asm volatile("cp.async.wait_group 1;\n");
            __syncthreads();
            sl = (sl == 2) ? 0 : sl + 1;
            sc = (sc == 2) ? 0 : sc + 1;
        }
#pragma unroll
        for (int mi = 0; mi < 4; mi++) {
            int m = m0 + wm * 64 + mi * 16 + g;
#pragma unroll
            for (int ni = 0; ni < 4; ni++) {
                int n = n0 + wn * 32 + ni * 8 + tig * 2;
                *(float2*)&CV[(size_t)m * N + n] =
                    make_float2(acc[mi][ni][0], acc[mi][ni][1]);
                *(float2*)&CV[(size_t)(m + 8) * N + n] =
                    make_float2(acc[mi][ni][2], acc[mi][ni][3]);
            }
        }
    }
}

// ---------------- 1xTF32 tensor-core GEMM, 3-stage cp.async pipeline ---------
template <bool RELU>
__global__ __launch_bounds__(256, 2) void gemm_tf1(
    const uint32_t* __restrict__ Ahi, const uint32_t* __restrict__ Bhi,
    float* __restrict__ C, int M, int N, int K,
    long sA, long sB, long sC, const float* __restrict__ bias) {
    extern __shared__ uint32_t smp[];
    Ahi += (size_t)blockIdx.z * sA;
    Bhi += (size_t)blockIdx.z * sB;
    C += (size_t)blockIdx.z * sC;
    int m0 = blockIdx.y * 128, n0 = blockIdx.x * 128;
    int tid = threadIdx.x, lane = tid & 31, w = tid >> 5;
    int wm = w & 1, wn = w >> 1;
    int g = lane >> 2, tig = lane & 3;
    float acc[4][4][4] = {};

    int crow = tid >> 4;
    int col0 = (tid & 15) * 4;
    uint32_t sbase = smem_u32(smp);
    const uint32_t STAGE_B = T1_STAGE_U32 * 4;
    uint32_t offA = ((0 * 16 + crow) * 136 + col0) * 4;
    uint32_t offB = ((1 * 16 + crow) * 136 + col0) * 4;

    int nt = K / 16;
#pragma unroll
    for (int p = 0; p < 2; p++) {
        uint32_t dst = sbase + p * STAGE_B;
        const uint32_t* ga = &Ahi[(size_t)(p * 16 + crow) * M + m0 + col0];
        const uint32_t* gb = &Bhi[(size_t)(p * 16 + crow) * N + n0 + col0];
        cpasync16(dst + offA, ga);
        cpasync16(dst + offA + 256, ga + 64);
        cpasync16(dst + offB, gb);
        cpasync16(dst + offB + 256, gb + 64);
        asm volatile("cp.async.commit_group;\n");
    }
    asm volatile("cp.async.wait_group 1;\n");
    __syncthreads();

    int sl = 2, sc = 0;
    for (int t = 0; t < nt; t++) {
        if (t + 2 < nt) {
            uint32_t dst = sbase + sl * STAGE_B;
            const uint32_t* ga = &Ahi[(size_t)((t + 2) * 16 + crow) * M + m0 + col0];
            const uint32_t* gb = &Bhi[(size_t)((t + 2) * 16 + crow) * N + n0 + col0];
            cpasync16(dst + offA, ga);
            cpasync16(dst + offA + 256, ga + 64);
            cpasync16(dst + offB, gb);
            cpasync16(dst + offB + 256, gb + 64);
        }
        asm volatile("cp.async.commit_group;\n");
        const uint32_t* As = smp + sc * T1_STAGE_U32;
        const uint32_t* Bs = As + 16 * 136;
#pragma unroll
        for (int kk = 0; kk < 16; kk += 8) {
            uint32_t af[4][4];
#pragma unroll
            for (int mi = 0; mi < 4; mi++) {
                int mb = wm * 64 + mi * 16 + g;
                af[mi][0] = As[(kk + tig) * 136 + mb];
                af[mi][1] = As[(kk + tig) * 136 + mb + 8];
                af[mi][2] = As[(kk + tig + 4) * 136 + mb];
                af[mi][3] = As[(kk + tig + 4) * 136 + mb + 8];
            }
#pragma unroll
            for (int ni = 0; ni < 4; ni++) {
                int nb = wn * 32 + ni * 8 + g;
                uint32_t bf[2];
                bf[0] = Bs[(kk + tig) * 136 + nb];
                bf[1] = Bs[(kk + tig + 4) * 136 + nb];
#pragma unroll
                for (int mi = 0; mi < 4; mi++) mma8(acc[mi][ni], af[mi], bf);
            }
        }
        asm volatile("cp.async.wait_group 1;\n");
        __syncthreads();
        sl = (sl == 2) ? 0 : sl + 1;
        sc = (sc == 2) ? 0 : sc + 1;
    }
#pragma unroll
    for (int mi = 0; mi < 4; mi++) {
        int m = m0 + wm * 64 + mi * 16 + g;
#pragma unroll
        for (int ni = 0; ni < 4; ni++) {
            int n = n0 + wn * 32 + ni * 8 + tig * 2;
            float b0 = bias ? bias[n] : 0.0f;
            float b1 = bias ? bias[n + 1] : 0.0f;
            float v0 = acc[mi][ni][0] + b0, v1 = acc[mi][ni][1] + b1;
            float v2 = acc[mi][ni][2] + b0, v3 = acc[mi][ni][3] + b1;
            if (RELU) {
                v0 = fmaxf(v0, 0.0f); v1 = fmaxf(v1, 0.0f);
                v2 = fmaxf(v2, 0.0f); v3 = fmaxf(v3, 0.0f);
            }
            *(float2*)&C[(size_t)m * N + n] = make_float2(v0, v1);
            *(float2*)&C[(size_t)(m + 8) * N + n] = make_float2(v2, v3);
        }
    }
}

// ---------------- fused attention, descending k + provable early break -------
// Masked tiles first (max saturates ~1e12). Once all remaining tiles are fully
// below the diagonal AND the Cauchy-Schwarz bound proves every row's tile-max
// is < mo-104 (exp underflows to exactly 0.0f), we BREAK: remaining tiles are
// bit-exact no-ops. Scores chain/mask/reductions FROZEN.
struct __align__(16) AttnSmem {
    float qs[64][132];      // [f][q]
    uint32_t Ps[128][68];   // [q][k]; rows 0-63 alias ks[f][k]
    uint32_t vhi[64][72];   // [k][f] tf32
    float sm_m[128];
    float sm_l[128];
    float sm_sc[128];
    float kpfx[16];         // prefix max of tile key-norms
    float lmin[16];         // per-ty local min of running maxes
    float mo_min;
    int active[2];
};

__global__ __launch_bounds__(256, 2) void attn_fused() {
    extern __shared__ char smraw[];
    AttnSmem* S = (AttnSmem*)smraw;
    float(*ks)[68] = (float(*)[68])S->Ps;
    int bh = blockIdx.y;
    int b = bh / HH, h = bh % HH;
    int q0 = blockIdx.x * 128;
    const float* qp = g_q + (size_t)b * TT * EE + h * FFDIM;
    const float* kp = g_k + (size_t)b * TT * EE + h * FFDIM;
    const float* vp = g_v + (size_t)b * TT * EE + h * FFDIM;

    int tid = threadIdx.x;
    int ty = tid >> 4, tx = tid & 15;
    int lane = tid & 31, w = tid >> 5;
    int wm = w >> 1, wn = w & 1;
    int g = lane >> 2, tig = lane & 3;
    int ar = tid >> 2;
    int ac4 = (tid & 3) * 4;
    int vr = tid >> 2;
    int vc = (tid & 3) * 16;
    float qmaxv = g_qmax[bh * 8 + blockIdx.x];

    // load Q tile (once)
#pragma unroll
    for (int c0 = 0; c0 < 64; c0 += 16) {
#pragma unroll
        for (int ri = 0; ri < 2; ri++) {
            int r = ar + ri * 64;
            const float4 va = *(const float4*)&qp[(size_t)(q0 + r) * EE + c0 + ac4];
            S->qs[c0 + ac4 + 0][r] = va.x;
            S->qs[c0 + ac4 + 1][r] = va.y;
            S->qs[c0 + ac4 + 2][r] = va.z;
            S->qs[c0 + ac4 + 3][r] = va.w;
        }
    }
    if (tid < 128) {
        S->sm_m[tid] = -INFINITY;
        S->sm_l[tid] = 0.0f;
    }
    if (tid < 2) S->active[tid] = 0;
    if (tid == 0) {
        float pm = 0.0f;
#pragma unroll
        for (int t = 0; t < 16; t++) {
            pm = fmaxf(pm, g_kmax[bh * 16 + t]);
            S->kpfx[t] = pm;
        }
        S->mo_min = -INFINITY;
    }
    // prologue: last tile (kt=15) K,V into smem
    {
        int k0 = TT - 64;
#pragma unroll
        for (int c = 0; c < 4; c++) {
            const float4 vb = *(const float4*)&kp[(size_t)(k0 + ar) * EE + c * 16 + ac4];
            ks[c * 16 + ac4 + 0][ar] = vb.x;
            ks[c * 16 + ac4 + 1][ar] = vb.y;
            ks[c * 16 + ac4 + 2][ar] = vb.z;
            ks[c * 16 + ac4 + 3][ar] = vb.w;
        }
#pragma unroll
        for (int j = 0; j < 4; j++) {
            const float4 v = *(const float4*)&vp[(size_t)(k0 + vr) * EE + vc + j * 4];
            uint4 t;
            t.x = f2tf(v.x); t.y = f2tf(v.y); t.z = f2tf(v.z); t.w = f2tf(v.w);
            *(uint4*)&S->vhi[vr][vc + j * 4] = t;
        }
    }
    float acc[2][4][4] = {};
    __syncthreads();

    for (int kt = TT / 64 - 1; kt >= 0; kt--) {
        // provable early break: all remaining tiles fully below diagonal AND
        // 2*|Q||K|/8 + 104 < min running max -> remaining tiles are exact no-ops
        if (kt * 64 + 63 <= q0 &&
            0.25f * qmaxv * S->kpfx[kt] + 104.0f < S->mo_min) break;

        int k0 = kt * 64;
        int par = kt & 1;
        bool more = (kt > 0);
        float4 kr[4], vrg[4];
        if (more) {
#pragma unroll
            for (int c = 0; c < 4; c++)
                kr[c] = *(const float4*)&kp[(size_t)(k0 - 64 + ar) * EE + c * 16 + ac4];
#pragma unroll
            for (int j = 0; j < 4; j++)
                vrg[j] = *(const float4*)&vp[(size_t)(k0 - 64 + vr) * EE + vc + j * 4];
        }

        // scores: 8 rows x 4 cols, ascending f (FROZEN fp32 chain)
        float s[8][4] = {};
#pragma unroll
        for (int f = 0; f < 64; f++) {
            float a[8], bv[4];
            *(float4*)&a[0] = *(const float4*)&S->qs[f][ty * 8];
            *(float4*)&a[4] = *(const float4*)&S->qs[f][ty * 8 + 4];
            *(float4*)&bv[0] = *(const float4*)&ks[f][tx * 4];
#pragma unroll
            for (int i = 0; i < 8; i++)
#pragma unroll
                for (int j = 0; j < 4; j++) s[i][j] += a[i] * bv[j];
        }
#pragma unroll
        for (int i = 0; i < 8; i++) {
            int qg = q0 + ty * 8 + i;
#pragma unroll
            for (int j = 0; j < 4; j++) {
                int kg = k0 + tx * 4 + j;
                float m = (kg > qg) ? (1.0f - 1.0e9f) : 1.0f;
                s[i][j] = s[i][j] * m * 0.125f;
            }
        }
        float tm[8];
#pragma unroll
        for (int i = 0; i < 8; i++) {
            float v = fmaxf(fmaxf(s[i][0], s[i][1]), fmaxf(s[i][2], s[i][3]));
#pragma unroll
            for (int o = 8; o > 0; o >>= 1) v = fmaxf(v, __shfl_xor_sync(0xffffffffu, v, o));
            tm[i] = v;
        }
        if (tx == 0) {
            int rowact = 0;
            float lm = INFINITY;
#pragma unroll
            for (int i = 0; i < 8; i++) {
                int row = ty * 8 + i;
                float mo = S->sm_m[row];
                float mn = fmaxf(mo, tm[i]);
                S->sm_sc[row] = __expf(mo - mn);
                S->sm_m[row] = mn;
                lm = fminf(lm, mn);
                if (tm[i] - mn > -104.0f) rowact = 1;
            }
            S->lmin[ty] = lm;
            if (rowact) atomicOr(&S->active[par], 1);
        }
        __syncthreads();  // A

        int act = S->active[par];
        if (tid == 0) {
            S->active[par ^ 1] = 0;
            float mm = S->lmin[0];
#pragma unroll
            for (int i2 = 1; i2 < 16; i2++) mm = fminf(mm, S->lmin[i2]);
            S->mo_min = mm;
        }

        if (act) {
            unsigned hm = (lane & 16) ? 0xffff0000u : 0x0000ffffu;
#pragma unroll
            for (int i = 0; i < 8; i++) {
                int row = ty * 8 + i;
                float mn = S->sm_m[row];
                if (tm[i] - mn > -104.0f) {
                    float p0 = __expf(s[i][0] - mn);
                    float p1 = __expf(s[i][1] - mn);
                    float p2 = __expf(s[i][2] - mn);
                    float p3 = __expf(s[i][3] - mn);
                    float rs = p0 + p1 + p2 + p3;
                    *(uint4*)&S->Ps[row][tx * 4] =
                        make_uint4(f2tf(p0), f2tf(p1), f2tf(p2), f2tf(p3));
#pragma unroll
                    for (int o = 8; o > 0; o >>= 1) rs += __shfl_xor_sync(hm, rs, o);
                    if (tx == 0) S->sm_l[row] = S->sm_l[row] * S->sm_sc[row] + rs;
                } else {
                    *(uint4*)&S->Ps[row][tx * 4] = make_uint4(0, 0, 0, 0);
                }
            }
            __syncthreads();  // B

#pragma unroll
            for (int mi = 0; mi < 2; mi++) {
                int row = wm * 32 + mi * 16 + g;
                float s0 = S->sm_sc[row], s1 = S->sm_sc[row + 8];
#pragma unroll
                for (int ni = 0; ni < 4; ni++) {
                    acc[mi][ni][0] *= s0; acc[mi][ni][1] *= s0;
                    acc[mi][ni][2] *= s1; acc[mi][ni][3] *= s1;
                }
            }
#pragma unroll
            for (int kk = 0; kk < 64; kk += 8) {
                uint32_t af[2][4];
#pragma unroll
                for (int mi = 0; mi < 2; mi++) {
                    int mb = wm * 32 + mi * 16 + g;
                    af[mi][0] = S->Ps[mb][kk + tig];
                    af[mi][1] = S->Ps[mb + 8][kk + tig];
                    af[mi][2] = S->Ps[mb][kk + tig + 4];
                    af[mi][3] = S->Ps[mb + 8][kk + tig + 4];
                }
#pragma unroll
                for (int ni = 0; ni < 4; ni++) {
                    int nb = wn * 32 + ni * 8 + g;
                    uint32_t bf[2];
                    bf[0] = S->vhi[kk + tig][nb];
                    bf[1] = S->vhi[kk + tig + 4][nb];
#pragma unroll
                    for (int mi = 0; mi < 2; mi++) mma8(acc[mi][ni], af[mi], bf);
                }
            }
            __syncthreads();  // C
        }

        if (more) {
#pragma unroll
            for (int c = 0; c < 4; c++) {
                ks[c * 16 + ac4 + 0][ar] = kr[c].x;
                ks[c * 16 + ac4 + 1][ar] = kr[c].y;
                ks[c * 16 + ac4 + 2][ar] = kr[c].z;
                ks[c * 16 + ac4 + 3][ar] = kr[c].w;
            }
#pragma unroll
            for (int j = 0; j < 4; j++) {
                uint4 t;
                t.x = f2tf(vrg[j].x); t.y = f2tf(vrg[j].y);
                t.z = f2tf(vrg[j].z); t.w = f2tf(vrg[j].w);
                *(uint4*)&S->vhi[vr][vc + j * 4] = t;
            }
        }
        __syncthreads();  // D
    }
    // epilogue: O /= l, write transposed tf32 directly into g_athi [B][E][T]
    {
        size_t obase = (size_t)b * EE * TT + (size_t)h * 64 * TT;
#pragma unroll
        for (int mi = 0; mi < 2; mi++) {
            int row = wm * 32 + mi * 16 + g;
            float i0 = 1.0f / S->sm_l[row];
            float i1 = 1.0f / S->sm_l[row + 8];
            int m = q0 + row;
#pragma unroll
            for (int ni = 0; ni < 4; ni++) {
                int n = wn * 32 + ni * 8 + tig * 2;
                g_athi[obase + (size_t)n * TT + m] = f2tf(acc[mi][ni][0] * i0);
                g_athi[obase + (size_t)(n + 1) * TT + m] = f2tf(acc[mi][ni][1] * i0);
                g_athi[obase + (size_t)n * TT + m + 8] = f2tf(acc[mi][ni][2] * i1);
                g_athi[obase + (size_t)(n + 1) * TT + m + 8] = f2tf(acc[mi][ni][3] * i1);
            }
        }
    }
}

// ---------------- LayerNorm over whole [T,E] plane per batch -----------------
__global__ __launch_bounds__(256) void ln_reduce(const float* __restrict__ in1,
                                                 const float* __restrict__ in2) {
    int b = blockIdx.y;
    const float* p1 = in1 + (size_t)b * LN_N;
    const float* p2 = in2 + (size_t)b * LN_N;
    const int chunk = (int)(LN_N / 64);
    size_t base = (size_t)blockIdx.x * chunk;
    double s = 0.0, sq = 0.0;
    for (int i = threadIdx.x * 4; i < chunk; i += 256 * 4) {
        float4 a = *(const float4*)&p1[base + i];
        float4 c = *(const float4*)&p2[base + i];
        float x0 = a.x + c.x, x1 = a.y + c.y, x2 = a.z + c.z, x3 = a.w + c.w;
        s += (double)x0 + (double)x1 + (double)x2 + (double)x3;
        sq += (double)x0 * x0 + (double)x1 * x1 + (double)x2 * x2 + (double)x3 * x3;
    }
    __shared__ double sh[256], shq[256];
    int tid = threadIdx.x;
    sh[tid] = s;
    shq[tid] = sq;
    __syncthreads();
    for (int o = 128; o > 0; o >>= 1) {
        if (tid < o) {
            sh[tid] += sh[tid + o];
            shq[tid] += shq[tid + o];
        }
        __syncthreads();
    }
    if (tid == 0) {
        g_part[(b * 64 + blockIdx.x) * 2] = sh[0];
        g_part[(b * 64 + blockIdx.x) * 2 + 1] = shq[0];
    }
}

__global__ void ln_finalize() {
    int b = blockIdx.x;
    int tid = threadIdx.x;
    __shared__ double sh[64], shq[64];
    sh[tid] = g_part[(b * 64 + tid) * 2];
    shq[tid] = g_part[(b * 64 + tid) * 2 + 1];
    __syncthreads();
    for (int o = 32; o > 0; o >>= 1) {
        if (tid < o) {
            sh[tid] += sh[tid + o];
            shq[tid] += shq[tid + o];
        }
        __syncthreads();
    }
    if (tid == 0) {
        double n = (double)LN_N;
        double mean = sh[0] / n;
        double var = shq[0] / n - mean * mean;
        g_stats[b * 2] = (float)mean;
        g_stats[b * 2 + 1] = (float)(1.0 / sqrt(var + 1e-5));
    }
}

// LN1 fused with transpose: writes z1 AND transposed tf32 athi
__global__ __launch_bounds__(256) void ln_norm_t(
    const float* __restrict__ in1, const float* __restrict__ in2,
    const float* __restrict__ w, const float* __restrict__ bia,
    float* __restrict__ out, uint32_t* __restrict__ ohi) {
    __shared__ float t[32][33];
    int m0 = blockIdx.y * 32, k0 = blockIdx.x * 32;
    int tx = threadIdx.x & 31, ty = threadIdx.x >> 5;
    int b = m0 / TT;
    float mean = g_stats[b * 2];
    float rstd = g_stats[b * 2 + 1];
#pragma unroll
    for (int i = ty; i < 32; i += 8) {
        int row = m0 + i;
        size_t idx = (size_t)row * EE + k0 + tx;
        size_t te = (size_t)(row % TT) * EE + k0 + tx;
        float v = (in1[idx] + in2[idx] - mean) * rstd * w[te] + bia[te];
        out[idx] = v;
        t[i][tx] = v;
    }
    __syncthreads();
#pragma unroll
    for (int i = ty; i < 32; i += 8) {
        ohi[(size_t)(k0 + i) * (BB * TT) + m0 + tx] = f2tf(t[tx][i]);
    }
}

// transpose + tf32 (x feed)
__global__ __launch_bounds__(256) void transpose_tf(
    const float* __restrict__ in, uint32_t* __restrict__ ohi, int M, int K) {
    __shared__ float t[32][33];
    int m0 = blockIdx.y * 32, k0 = blockIdx.x * 32;
    int tx = threadIdx.x & 31, ty = threadIdx.x >> 5;
#pragma unroll
    for (int i = ty; i < 32; i += 8) t[i][tx] = in[(size_t)(m0 + i) * K + k0 + tx];
    __syncthreads();
#pragma unroll
    for (int i = ty; i < 32; i += 8) {
        ohi[(size_t)(k0 + i) * M + m0 + tx] = f2tf(t[tx][i]);
    }
}

__global__ __launch_bounds__(256) void ln_norm(const float* __restrict__ in1,
                                               const float* __restrict__ in2,
                                               const float* __restrict__ w,
                                               const float* __restrict__ bia,
                                               float* __restrict__ out) {
    size_t i = ((size_t)blockIdx.x * blockDim.x + threadIdx.x) * 4;
    if (i >= (size_t)BB * LN_N) return;
    int b = (int)(i / LN_N);
    size_t te = i % LN_N;
    float mean = g_stats[b * 2];
    float rstd = g_stats[b * 2 + 1];
    float4 a = *(const float4*)&in1[i];
    float4 c = *(const float4*)&in2[i];
    float4 ww = *(const float4*)&w[te];
    float4 bb = *(const float4*)&bia[te];
    float4 o;
    o.x = (a.x + c.x - mean) * rstd * ww.x + bb.x;
    o.y = (a.y + c.y - mean) * rstd * ww.y + bb.y;
    o.z = (a.z + c.z - mean) * rstd * ww.z + bb.z;
    o.w = (a.w + c.w - mean) * rstd * ww.w + bb.w;
    *(float4*)&out[i] = o;
}

// ---------------- launch -----------------------------------------------------
extern "C" void kernel_launch(void* const* d_in, const int* in_sizes, int n_in,
                              void* d_out, int out_size) {
    const float* x = (const float*)d_in[0];
    const float* q_w = (const float*)d_in[1];
    const float* k_w = (const float*)d_in[2];
    const float* v_w = (const float*)d_in[3];
    const float* fr_w = (const float*)d_in[4];
    const float* ff_w = (const float*)d_in[5];
    const float* ff_b = (const float*)d_in[6];
    const float* ln1_w = (const float*)d_in[7];
    const float* ln1_b = (const float*)d_in[8];
    const float* ln2_w = (const float*)d_in[9];
    const float* ln2_b = (const float*)d_in[10];
    float* out = (float*)d_out;

    float *p_wq, *p_wk, *p_q, *p_k, *p_v, *p_zf, *p_z1, *p_z2;
    uint32_t *p_wvhi, *p_wffhi, *p_frhi, *p_athi;
    cudaGetSymbolAddress((void**)&p_wq, g_wq);
    cudaGetSymbolAddress((void**)&p_wk, g_wk);
    cudaGetSymbolAddress((void**)&p_q, g_q);
    cudaGetSymbolAddress((void**)&p_k, g_k);
    cudaGetSymbolAddress((void**)&p_v, g_v);
    cudaGetSymbolAddress((void**)&p_zf, g_zf);
    cudaGetSymbolAddress((void**)&p_z1, g_z1);
    cudaGetSymbolAddress((void**)&p_z2, g_z2);
    cudaGetSymbolAddress((void**)&p_wvhi, g_wvhi);
    cudaGetSymbolAddress((void**)&p_wffhi, g_wffhi);
    cudaGetSymbolAddress((void**)&p_frhi, g_frhi);
    cudaGetSymbolAddress((void**)&p_athi, g_athi);

    const size_t SMP = 3 * T1_STAGE_U32 * sizeof(uint32_t);
    const size_t SMA = sizeof(AttnSmem);
    cudaFuncSetAttribute(attn_fused, cudaFuncAttributeMaxDynamicSharedMemorySize, (int)SMA);
    cudaFuncSetAttribute(gemm_qkv, cudaFuncAttributeMaxDynamicSharedMemorySize, (int)SMP);
    cudaFuncSetAttribute(gemm_tf1<false>, cudaFuncAttributeMaxDynamicSharedMemorySize, (int)SMP);
    cudaFuncSetAttribute(gemm_tf1<true>, cudaFuncAttributeMaxDynamicSharedMemorySize, (int)SMP);

    // 1) merged weight repacks
    int repack_total = EE * EE + BB * EE * EE;
    repack_all<<<(repack_total + 255) / 256, 256>>>(q_w, k_w, v_w, ff_w, fr_w);

    // 2) transpose x (feeds V path of merged kernel)
    dim3 gtx(EE / 32, (BB * TT) / 32, 1);
    transpose_tf<<<gtx, 256>>>(x, p_athi, BB * TT, EE);

    // 3) merged QKV
    dim3 gqkv(EE / 128, (BB * TT) / 128, 3);
    gemm_qkv<<<gqkv, 256, SMP>>>(x, p_wq, p_wk, p_q, p_k,
                                 p_athi, p_wvhi, p_v, BB * TT, EE, EE);

    // 3b) Q/K norm maxima for provable tile skip
    dim3 gn(24, BB * HH, 1);
    qk_norms<<<gn, 128>>>();

    // 4) fused attention (descending k, provable early break)
    dim3 gat(TT / 128, BB * HH, 1);
    attn_fused<<<gat, 256, SMA>>>();

    // 5) zf[b] = zm[b] @ fr[b]
    dim3 gfr(EE / 128, TT / 128, BB);
    gemm_tf1<false><<<gfr, 256, SMP>>>(p_athi, p_frhi, p_zf,
                                       TT, EE, EE, (long)TT * EE, (long)EE * EE,
                                       (long)TT * EE, nullptr);

    // 6) LN1 over x + zf -> z1, fused with transpose to athi
    dim3 gred(64, BB, 1);
    ln_reduce<<<gred, 256>>>(x, p_zf);
    ln_finalize<<<BB, 64>>>();
    ln_norm_t<<<gtx, 256>>>(x, p_zf, ln1_w, ln1_b, p_z1, p_athi);

    // 7) FFN: z2 = relu(z1 @ ff_w^T + ff_b)
    dim3 gv(EE / 128, (BB * TT) / 128, 1);
    gemm_tf1<true><<<gv, 256, SMP>>>(p_athi, p_wffhi, p_z2,
                                     BB * TT, EE, EE, 0, 0, 0, ff_b);

    // 8) LN2 over z1 + z2 -> out
    ln_reduce<<<gred, 256>>>(p_z1, p_z2);
    ln_finalize<<<BB, 64>>>();
    size_t total = (size_t)BB * LN_N;
    ln_norm<<<(unsigned)((total / 4 + 255) / 256), 256>>>(p_z1, p_z2, ln2_w, ln2_b, out);
}

// round 17
// speedup vs baseline: 1.1371x; 1.0232x over previous
#include <cuda_runtime.h>
#include <math.h>
#include <stdint.h>

#define BB 4
#define TT 1024
#define EE 1024
#define HH 16
#define FFDIM 64
#define LN_N ((size_t)TT * EE)

// ---------------- scratch (static device globals; no allocation) -------------
__device__ float g_wq[EE * EE];
__device__ float g_wk[EE * EE];
__device__ float g_q[BB * TT * EE];
__device__ float g_k[BB * TT * EE];
__device__ float g_v[BB * TT * EE];
__device__ float g_zf[BB * TT * EE];
__device__ float g_z1[BB * TT * EE];
__device__ float g_z2[BB * TT * EE];
__device__ float g_stats[BB * 2];
__device__ double g_lnacc[2][BB][2];       // [which][batch][sum, sumsq]
__device__ uint32_t g_wvhi[EE * EE];
__device__ uint32_t g_wffhi[EE * EE];
__device__ uint32_t g_frhi[BB * EE * EE];
__device__ uint32_t g_athi[BB * TT * EE];  // transposed activation [K][M]
__device__ float g_kmax[BB * HH * 16];     // per (bh, k-tile) max key L2 norm
__device__ float g_qmax[BB * HH * 8];      // per (bh, q-block) max query L2 norm

// ---------------- helpers ----------------------------------------------------
__device__ __forceinline__ uint32_t f2tf(float x) {
    uint32_t r;
    asm("cvt.rna.tf32.f32 %0, %1;" : "=r"(r) : "f"(x));
    return r;
}

__device__ __forceinline__ void mma8(float c[4], const uint32_t a[4], const uint32_t b[2]) {
    asm volatile(
        "mma.sync.aligned.m16n8k8.row.col.f32.tf32.tf32.f32 "
        "{%0,%1,%2,%3}, {%4,%5,%6,%7}, {%8,%9}, {%0,%1,%2,%3};\n"
        : "+f"(c[0]), "+f"(c[1]), "+f"(c[2]), "+f"(c[3])
        : "r"(a[0]), "r"(a[1]), "r"(a[2]), "r"(a[3]), "r"(b[0]), "r"(b[1]));
}

__device__ __forceinline__ uint32_t smem_u32(const void* p) {
    return (uint32_t)__cvta_generic_to_shared(p);
}
__device__ __forceinline__ void cpasync16(uint32_t dst, const void* src) {
    asm volatile("cp.async.ca.shared.global [%0], [%1], 16;\n" ::"r"(dst), "l"(src));
}

// ---------------- merged weight repacks + per-launch accumulator reset -------
__global__ void repack_all(const float* __restrict__ qw,
                           const float* __restrict__ kw,
                           const float* __restrict__ vw,
                           const float* __restrict__ ffw,
                           const float* __restrict__ frw) {
    int idx = blockIdx.x * blockDim.x + threadIdx.x;
    if (idx < EE * EE) {
        int e = idx / EE, n = idx % EE;
        int h = n >> 6, f = n & 63;
        int src = h * (EE * FFDIM) + e * FFDIM + f;
        g_wq[idx] = qw[src];
        g_wk[idx] = kw[src];
        g_wvhi[idx] = f2tf(vw[src]);
        g_wffhi[idx] = f2tf(ffw[n * EE + e]);
    }
    int idx2 = idx - EE * EE;
    if (idx2 >= 0 && idx2 < BB * EE * EE) g_frhi[idx2] = f2tf(frw[idx2]);
    // per-launch resets (graph-replay safe)
    if (idx < BB * HH * 8) ((int*)g_qmax)[idx] = 0;
    if (idx < BB * HH * 16) ((int*)g_kmax)[idx] = 0;
    if (idx < 2 * BB * 2) ((double*)g_lnacc)[idx] = 0.0;
}

// ---------------- merged QKV GEMM (FROZEN fp32 chain for Q,K) ----------------
// Q/K epilogues also produce the per-row-norm maxima used by attn's provable
// tile skip (atomicMax on non-negative floats via int compare).
#define T1_STAGE_U32 (2 * 16 * 136)
__global__ __launch_bounds__(256, 2) void gemm_qkv(
    const float* __restrict__ A, const float* __restrict__ B0,
    const float* __restrict__ B1, float* __restrict__ C0, float* __restrict__ C1,
    const uint32_t* __restrict__ Ahi, const uint32_t* __restrict__ Bhi,
    float* __restrict__ CV, int M, int N, int K) {
    extern __shared__ uint32_t smp[];
    int m0 = blockIdx.y * 128, n0 = blockIdx.x * 128;
    int tid = threadIdx.x;

    if (blockIdx.z < 2) {
        const float* Bm = blockIdx.z ? B1 : B0;
        float* C = blockIdx.z ? C1 : C0;
        float* Asf = (float*)smp;
        float* Bsf = Asf + 2 * 16 * 132;
        int ty = tid >> 4, tx = tid & 15;
        float acc[8][8] = {};
        int ar = tid >> 2;
        int ac4 = (tid & 3) * 4;
        int bk = tid >> 5;
        int bc4 = (tid & 31) * 4;

        uint32_t bd0[2], bd1[2];
        bd0[0] = smem_u32(&Bsf[0 * 2048 + bk * 128 + bc4]);
        bd0[1] = smem_u32(&Bsf[1 * 2048 + bk * 128 + bc4]);
        bd1[0] = smem_u32(&Bsf[0 * 2048 + (bk + 8) * 128 + bc4]);
        bd1[1] = smem_u32(&Bsf[1 * 2048 + (bk + 8) * 128 + bc4]);

        cpasync16(bd0[0], &Bm[(size_t)bk * N + n0 + bc4]);
        cpasync16(bd1[0], &Bm[(size_t)(bk + 8) * N + n0 + bc4]);
        asm volatile("cp.async.commit_group;\n");
        float4 ra0 = *(const float4*)&A[(size_t)(m0 + ar) * K + ac4];
        float4 ra1 = *(const float4*)&A[(size_t)(m0 + ar + 64) * K + ac4];
        Asf[(ac4 + 0) * 132 + ar] = ra0.x; Asf[(ac4 + 1) * 132 + ar] = ra0.y;
        Asf[(ac4 + 2) * 132 + ar] = ra0.z; Asf[(ac4 + 3) * 132 + ar] = ra0.w;
        Asf[(ac4 + 0) * 132 + ar + 64] = ra1.x; Asf[(ac4 + 1) * 132 + ar + 64] = ra1.y;
        Asf[(ac4 + 2) * 132 + ar + 64] = ra1.z; Asf[(ac4 + 3) * 132 + ar + 64] = ra1.w;
        asm volatile("cp.async.wait_group 0;\n");
        __syncthreads();

        int nt = K / 16;
        for (int t = 0; t < nt; t++) {
            int s = t & 1;
            if (t + 1 < nt) {
                int k0 = (t + 1) * 16;
                cpasync16(bd0[s ^ 1], &Bm[(size_t)(k0 + bk) * N + n0 + bc4]);
                cpasync16(bd1[s ^ 1], &Bm[(size_t)(k0 + bk + 8) * N + n0 + bc4]);
                asm volatile("cp.async.commit_group;\n");
                ra0 = *(const float4*)&A[(size_t)(m0 + ar) * K + k0 + ac4];
                ra1 = *(const float4*)&A[(size_t)(m0 + ar + 64) * K + k0 + ac4];
            }
            const float* Asc = Asf + s * 2112;
            const float* Bsc = Bsf + s * 2048;
#pragma unroll
            for (int k = 0; k < 16; k++) {
                float a[8], b[8];
                *(float4*)&a[0] = *(const float4*)&Asc[k * 132 + ty * 8];
                *(float4*)&a[4] = *(const float4*)&Asc[k * 132 + ty * 8 + 4];
                *(float4*)&b[0] = *(const float4*)&Bsc[k * 128 + tx * 8];
                *(float4*)&b[4] = *(const float4*)&Bsc[k * 128 + tx * 8 + 4];
#pragma unroll
                for (int i = 0; i < 8; i++)
#pragma unroll
                    for (int j = 0; j < 8; j++) acc[i][j] += a[i] * b[j];
            }
            if (t + 1 < nt) {
                int s2 = s ^ 1;
                float* Asn = Asf + s2 * 2112;
                Asn[(ac4 + 0) * 132 + ar] = ra0.x; Asn[(ac4 + 1) * 132 + ar] = ra0.y;
                Asn[(ac4 + 2) * 132 + ar] = ra0.z; Asn[(ac4 + 3) * 132 + ar] = ra0.w;
                Asn[(ac4 + 0) * 132 + ar + 64] = ra1.x; Asn[(ac4 + 1) * 132 + ar + 64] = ra1.y;
                Asn[(ac4 + 2) * 132 + ar + 64] = ra1.z; Asn[(ac4 + 3) * 132 + ar + 64] = ra1.w;
                asm volatile("cp.async.wait_group 0;\n");
            }
            __syncthreads();
        }
#pragma unroll
        for (int i = 0; i < 8; i++) {
            int m = m0 + ty * 8 + i;
            *(float4*)&C[(size_t)m * N + n0 + tx * 8] = *(float4*)&acc[i][0];
            *(float4*)&C[(size_t)m * N + n0 + tx * 8 + 4] = *(float4*)&acc[i][4];
        }
        // fused row-norm maxima for attn skip bound (per head = 8 tx lanes)
        {
            float mxsq = 0.0f;
#pragma unroll
            for (int i = 0; i < 8; i++) {
                float ss = 0.0f;
#pragma unroll
                for (int j = 0; j < 8; j++) ss += acc[i][j] * acc[i][j];
#pragma unroll
                for (int o = 4; o > 0; o >>= 1) ss += __shfl_xor_sync(0xffffffffu, ss, o);
                mxsq = fmaxf(mxsq, ss);
            }
            if ((tx & 7) == 0) {
                float nrm = sqrtf(mxsq);
                int bb = m0 >> 10;
                int head = (n0 >> 6) + (tx >> 3);
                int bh = bb * HH + head;
                if (blockIdx.z == 0) {
                    int qb = (m0 & 1023) >> 7;
                    atomicMax((int*)&g_qmax[bh * 8 + qb], __float_as_int(nrm));
                } else {
                    int kt = ((m0 & 1023) >> 6) + (ty >= 8 ? 1 : 0);
                    atomicMax((int*)&g_kmax[bh * 16 + kt], __float_as_int(nrm));
                }
            }
        }
    } else {
        // 1xTF32 tensor path (V projection)
        int lane = tid & 31, w = tid >> 5;
        int wm = w & 1, wn = w >> 1;
        int g = lane >> 2, tig = lane & 3;
        float acc[4][4][4] = {};
        int crow = tid >> 4;
        int col0 = (tid & 15) * 4;
        uint32_t sbase = smem_u32(smp);
        const uint32_t STAGE_B = T1_STAGE_U32 * 4;
        uint32_t offA = ((0 * 16 + crow) * 136 + col0) * 4;
        uint32_t offB = ((1 * 16 + crow) * 136 + col0) * 4;

        int nt = K / 16;
#pragma unroll
        for (int p = 0; p < 2; p++) {
            uint32_t dst = sbase + p * STAGE_B;
            const uint32_t* ga = &Ahi[(size_t)(p * 16 + crow) * M + m0 + col0];
            const uint32_t* gb = &Bhi[(size_t)(p * 16 + crow) * N + n0 + col0];
            cpasync16(dst + offA, ga);
            cpasync16(dst + offA + 256, ga + 64);
            cpasync16(dst + offB, gb);
            cpasync16(dst + offB + 256, gb + 64);
            asm volatile("cp.async.commit_group;\n");
        }
        asm volatile("cp.async.wait_group 1;\n");
        __syncthreads();

        int sl = 2, sc = 0;
        for (int t = 0; t < nt; t++) {
            if (t + 2 < nt) {
                uint32_t dst = sbase + sl * STAGE_B;
                const uint32_t* ga = &Ahi[(size_t)((t + 2) * 16 + crow) * M + m0 + col0];
                const uint32_t* gb = &Bhi[(size_t)((t + 2) * 16 + crow) * N + n0 + col0];
                cpasync16(dst + offA, ga);
                cpasync16(dst + offA + 256, ga + 64);
                cpasync16(dst + offB, gb);
                cpasync16(dst + offB + 256, gb + 64);
            }
            asm volatile("cp.async.commit_group;\n");
            const uint32_t* As = smp + sc * T1_STAGE_U32;
            const uint32_t* Bs = As + 16 * 136;
#pragma unroll
            for (int kk = 0; kk < 16; kk += 8) {
                uint32_t af[4][4];
#pragma unroll
                for (int mi = 0; mi < 4; mi++) {
                    int mb = wm * 64 + mi * 16 + g;
                    af[mi][0] = As[(kk + tig) * 136 + mb];
                    af[mi][1] = As[(kk + tig) * 136 + mb + 8];
                    af[mi][2] = As[(kk + tig + 4) * 136 + mb];
                    af[mi][3] = As[(kk + tig + 4) * 136 + mb + 8];
                }
#pragma unroll
                for (int ni = 0; ni < 4; ni++) {
                    int nb = wn * 32 + ni * 8 + g;
                    uint32_t bf[2];
                    bf[0] = Bs[(kk + tig) * 136 + nb];
                    bf[1] = Bs[(kk + tig + 4) * 136 + nb];
#pragma unroll
                    for (int mi = 0; mi < 4; mi++) mma8(acc[mi][ni], af[mi], bf);
                }
            }
            asm volatile("cp.async.wait_group 1;\n");
            __syncthreads();
            sl = (sl == 2) ? 0 : sl + 1;
            sc = (sc == 2) ? 0 : sc + 1;
        }
#pragma unroll
        for (int mi = 0; mi < 4; mi++) {
            int m = m0 + wm * 64 + mi * 16 + g;
#pragma unroll
            for (int ni = 0; ni < 4; ni++) {
                int n = n0 + wn * 32 + ni * 8 + tig * 2;
                *(float2*)&CV[(size_t)m * N + n] =
                    make_float2(acc[mi][ni][0], acc[mi][ni][1]);
                *(float2*)&CV[(size_t)(m + 8) * N + n] =
                    make_float2(acc[mi][ni][2], acc[mi][ni][3]);
            }
        }
    }
}

// ---------------- 1xTF32 tensor-core GEMM + optional fused LN reduction ------
// If aux != nullptr, the epilogue accumulates sum and sumsq of (aux + C) into
// g_lnacc[lnw][batch] (double atomics; LN is the error-tolerant path).
template <bool RELU>
__global__ __launch_bounds__(256, 2) void gemm_tf1(
    const uint32_t* __restrict__ Ahi, const uint32_t* __restrict__ Bhi,
    float* __restrict__ C, int M, int N, int K,
    long sA, long sB, long sC, const float* __restrict__ bias,
    const float* __restrict__ aux, int lnw) {
    extern __shared__ uint32_t smp[];
    Ahi += (size_t)blockIdx.z * sA;
    Bhi += (size_t)blockIdx.z * sB;
    C += (size_t)blockIdx.z * sC;
    if (aux) aux += (size_t)blockIdx.z * sC;
    int m0 = blockIdx.y * 128, n0 = blockIdx.x * 128;
    int tid = threadIdx.x, lane = tid & 31, w = tid >> 5;
    int wm = w & 1, wn = w >> 1;
    int g = lane >> 2, tig = lane & 3;
    float acc[4][4][4] = {};

    int crow = tid >> 4;
    int col0 = (tid & 15) * 4;
    uint32_t sbase = smem_u32(smp);
    const uint32_t STAGE_B = T1_STAGE_U32 * 4;
    uint32_t offA = ((0 * 16 + crow) * 136 + col0) * 4;
    uint32_t offB = ((1 * 16 + crow) * 136 + col0) * 4;

    int nt = K / 16;
#pragma unroll
    for (int p = 0; p < 2; p++) {
        uint32_t dst = sbase + p * STAGE_B;
        const uint32_t* ga = &Ahi[(size_t)(p * 16 + crow) * M + m0 + col0];
        const uint32_t* gb = &Bhi[(size_t)(p * 16 + crow) * N + n0 + col0];
        cpasync16(dst + offA, ga);
        cpasync16(dst + offA + 256, ga + 64);
        cpasync16(dst + offB, gb);
        cpasync16(dst + offB + 256, gb + 64);
        asm volatile("cp.async.commit_group;\n");
    }
    asm volatile("cp.async.wait_group 1;\n");
    __syncthreads();

    int sl = 2, sc = 0;
    for (int t = 0; t < nt; t++) {
        if (t + 2 < nt) {
            uint32_t dst = sbase + sl * STAGE_B;
            const uint32_t* ga = &Ahi[(size_t)((t + 2) * 16 + crow) * M + m0 + col0];
            const uint32_t* gb = &Bhi[(size_t)((t + 2) * 16 + crow) * N + n0 + col0];
            cpasync16(dst + offA, ga);
            cpasync16(dst + offA + 256, ga + 64);
            cpasync16(dst + offB, gb);
            cpasync16(dst + offB + 256, gb + 64);
        }
        asm volatile("cp.async.commit_group;\n");
        const uint32_t* As = smp + sc * T1_STAGE_U32;
        const uint32_t* Bs = As + 16 * 136;
#pragma unroll
        for (int kk = 0; kk < 16; kk += 8) {
            uint32_t af[4][4];
#pragma unroll
            for (int mi = 0; mi < 4; mi++) {
                int mb = wm * 64 + mi * 16 + g;
                af[mi][0] = As[(kk + tig) * 136 + mb];
                af[mi][1] = As[(kk + tig) * 136 + mb + 8];
                af[mi][2] = As[(kk + tig + 4) * 136 + mb];
                af[mi][3] = As[(kk + tig + 4) * 136 + mb + 8];
            }
#pragma unroll
            for (int ni = 0; ni < 4; ni++) {
                int nb = wn * 32 + ni * 8 + g;
                uint32_t bf[2];
                bf[0] = Bs[(kk + tig) * 136 + nb];
                bf[1] = Bs[(kk + tig + 4) * 136 + nb];
#pragma unroll
                for (int mi = 0; mi < 4; mi++) mma8(acc[mi][ni], af[mi], bf);
            }
        }
        asm volatile("cp.async.wait_group 1;\n");
        __syncthreads();
        sl = (sl == 2) ? 0 : sl + 1;
        sc = (sc == 2) ? 0 : sc + 1;
    }
    double ls = 0.0, lsq = 0.0;
#pragma unroll
    for (int mi = 0; mi < 4; mi++) {
        int m = m0 + wm * 64 + mi * 16 + g;
#pragma unroll
        for (int ni = 0; ni < 4; ni++) {
            int n = n0 + wn * 32 + ni * 8 + tig * 2;
            float b0 = bias ? bias[n] : 0.0f;
            float b1 = bias ? bias[n + 1] : 0.0f;
            float v0 = acc[mi][ni][0] + b0, v1 = acc[mi][ni][1] + b1;
            float v2 = acc[mi][ni][2] + b0, v3 = acc[mi][ni][3] + b1;
            if (RELU) {
                v0 = fmaxf(v0, 0.0f); v1 = fmaxf(v1, 0.0f);
                v2 = fmaxf(v2, 0.0f); v3 = fmaxf(v3, 0.0f);
            }
            *(float2*)&C[(size_t)m * N + n] = make_float2(v0, v1);
            *(float2*)&C[(size_t)(m + 8) * N + n] = make_float2(v2, v3);
            if (aux) {
                float2 a0 = *(const float2*)&aux[(size_t)m * N + n];
                float2 a1 = *(const float2*)&aux[(size_t)(m + 8) * N + n];
                float x0 = a0.x + v0, x1 = a0.y + v1, x2 = a1.x + v2, x3 = a1.y + v3;
                ls += (double)x0 + (double)x1 + (double)x2 + (double)x3;
                lsq += (double)x0 * x0 + (double)x1 * x1 +
                       (double)x2 * x2 + (double)x3 * x3;
            }
        }
    }
    if (aux) {
        double* sh = (double*)smp;
        sh[tid] = ls;
        sh[256 + tid] = lsq;
        __syncthreads();
        for (int o = 128; o > 0; o >>= 1) {
            if (tid < o) {
                sh[tid] += sh[tid + o];
                sh[256 + tid] += sh[256 + tid + o];
            }
            __syncthreads();
        }
        if (tid == 0) {
            int bidx = (sC != 0) ? (int)blockIdx.z : (m0 >> 10);
            atomicAdd(&g_lnacc[lnw][bidx][0], sh[0]);
            atomicAdd(&g_lnacc[lnw][bidx][1], sh[256]);
        }
    }
}

// ---------------- fused attention, descending k + provable early break -------
struct __align__(16) AttnSmem {
    float qs[64][132];
    uint32_t Ps[128][68];   // rows 0-63 alias ks[f][k]
    uint32_t vhi[64][72];
    float sm_m[128];
    float sm_l[128];
    float sm_sc[128];
    float kpfx[16];
    float lmin[16];
    float mo_min;
    int active[2];
};

__global__ __launch_bounds__(256, 2) void attn_fused() {
    extern __shared__ char smraw[];
    AttnSmem* S = (AttnSmem*)smraw;
    float(*ks)[68] = (float(*)[68])S->Ps;
    int bh = blockIdx.y;
    int b = bh / HH, h = bh % HH;
    int q0 = blockIdx.x * 128;
    const float* qp = g_q + (size_t)b * TT * EE + h * FFDIM;
    const float* kp = g_k + (size_t)b * TT * EE + h * FFDIM;
    const float* vp = g_v + (size_t)b * TT * EE + h * FFDIM;

    int tid = threadIdx.x;
    int ty = tid >> 4, tx = tid & 15;
    int lane = tid & 31, w = tid >> 5;
    int wm = w >> 1, wn = w & 1;
    int g = lane >> 2, tig = lane & 3;
    int ar = tid >> 2;
    int ac4 = (tid & 3) * 4;
    int vr = tid >> 2;
    int vc = (tid & 3) * 16;
    float qmaxv = g_qmax[bh * 8 + blockIdx.x];

#pragma unroll
    for (int c0 = 0; c0 < 64; c0 += 16) {
#pragma unroll
        for (int ri = 0; ri < 2; ri++) {
            int r = ar + ri * 64;
            const float4 va = *(const float4*)&qp[(size_t)(q0 + r) * EE + c0 + ac4];
            S->qs[c0 + ac4 + 0][r] = va.x;
            S->qs[c0 + ac4 + 1][r] = va.y;
            S->qs[c0 + ac4 + 2][r] = va.z;
            S->qs[c0 + ac4 + 3][r] = va.w;
        }
    }
    if (tid < 128) {
        S->sm_m[tid] = -INFINITY;
        S->sm_l[tid] = 0.0f;
    }
    if (tid < 2) S->active[tid] = 0;
    if (tid == 0) {
        float pm = 0.0f;
#pragma unroll
        for (int t = 0; t < 16; t++) {
            pm = fmaxf(pm, g_kmax[bh * 16 + t]);
            S->kpfx[t] = pm;
        }
        S->mo_min = -INFINITY;
    }
    {
        int k0 = TT - 64;
#pragma unroll
        for (int c = 0; c < 4; c++) {
            const float4 vb = *(const float4*)&kp[(size_t)(k0 + ar) * EE + c * 16 + ac4];
            ks[c * 16 + ac4 + 0][ar] = vb.x;
            ks[c * 16 + ac4 + 1][ar] = vb.y;
            ks[c * 16 + ac4 + 2][ar] = vb.z;
            ks[c * 16 + ac4 + 3][ar] = vb.w;
        }
#pragma unroll
        for (int j = 0; j < 4; j++) {
            const float4 v = *(const float4*)&vp[(size_t)(k0 + vr) * EE + vc + j * 4];
            uint4 t;
            t.x = f2tf(v.x); t.y = f2tf(v.y); t.z = f2tf(v.z); t.w = f2tf(v.w);
            *(uint4*)&S->vhi[vr][vc + j * 4] = t;
        }
    }
    float acc[2][4][4] = {};
    __syncthreads();

    for (int kt = TT / 64 - 1; kt >= 0; kt--) {
        if (kt * 64 + 63 <= q0 &&
            0.25f * qmaxv * S->kpfx[kt] + 104.0f < S->mo_min) break;

        int k0 = kt * 64;
        int par = kt & 1;
        bool more = (kt > 0);
        float4 kr[4], vrg[4];
        if (more) {
#pragma unroll
            for (int c = 0; c < 4; c++)
                kr[c] = *(const float4*)&kp[(size_t)(k0 - 64 + ar) * EE + c * 16 + ac4];
#pragma unroll
            for (int j = 0; j < 4; j++)
                vrg[j] = *(const float4*)&vp[(size_t)(k0 - 64 + vr) * EE + vc + j * 4];
        }

        float s[8][4] = {};
#pragma unroll
        for (int f = 0; f < 64; f++) {
            float a[8], bv[4];
            *(float4*)&a[0] = *(const float4*)&S->qs[f][ty * 8];
            *(float4*)&a[4] = *(const float4*)&S->qs[f][ty * 8 + 4];
            *(float4*)&bv[0] = *(const float4*)&ks[f][tx * 4];
#pragma unroll
            for (int i = 0; i < 8; i++)
#pragma unroll
                for (int j = 0; j < 4; j++) s[i][j] += a[i] * bv[j];
        }
#pragma unroll
        for (int i = 0; i < 8; i++) {
            int qg = q0 + ty * 8 + i;
#pragma unroll
            for (int j = 0; j < 4; j++) {
                int kg = k0 + tx * 4 + j;
                float m = (kg > qg) ? (1.0f - 1.0e9f) : 1.0f;
                s[i][j] = s[i][j] * m * 0.125f;
            }
        }
        float tm[8];
#pragma unroll
        for (int i = 0; i < 8; i++) {
            float v = fmaxf(fmaxf(s[i][0], s[i][1]), fmaxf(s[i][2], s[i][3]));
#pragma unroll
            for (int o = 8; o > 0; o >>= 1) v = fmaxf(v, __shfl_xor_sync(0xffffffffu, v, o));
            tm[i] = v;
        }
        if (tx == 0) {
            int rowact = 0;
            float lm = INFINITY;
#pragma unroll
            for (int i = 0; i < 8; i++) {
                int row = ty * 8 + i;
                float mo = S->sm_m[row];
                float mn = fmaxf(mo, tm[i]);
                S->sm_sc[row] = __expf(mo - mn);
                S->sm_m[row] = mn;
                lm = fminf(lm, mn);
                if (tm[i] - mn > -104.0f) rowact = 1;
            }
            S->lmin[ty] = lm;
            if (rowact) atomicOr(&S->active[par], 1);
        }
        __syncthreads();  // A

        int act = S->active[par];
        if (tid == 0) {
            S->active[par ^ 1] = 0;
            float mm = S->lmin[0];
#pragma unroll
            for (int i2 = 1; i2 < 16; i2++) mm = fminf(mm, S->lmin[i2]);
            S->mo_min = mm;
        }

        if (act) {
            unsigned hm = (lane & 16) ? 0xffff0000u : 0x0000ffffu;
#pragma unroll
            for (int i = 0; i < 8; i++) {
                int row = ty * 8 + i;
                float mn = S->sm_m[row];
                if (tm[i] - mn > -104.0f) {
                    float p0 = __expf(s[i][0] - mn);
                    float p1 = __expf(s[i][1] - mn);
                    float p2 = __expf(s[i][2] - mn);
                    float p3 = __expf(s[i][3] - mn);
                    float rs = p0 + p1 + p2 + p3;
                    *(uint4*)&S->Ps[row][tx * 4] =
                        make_uint4(f2tf(p0), f2tf(p1), f2tf(p2), f2tf(p3));
#pragma unroll
                    for (int o = 8; o > 0; o >>= 1) rs += __shfl_xor_sync(hm, rs, o);
                    if (tx == 0) S->sm_l[row] = S->sm_l[row] * S->sm_sc[row] + rs;
                } else {
                    *(uint4*)&S->Ps[row][tx * 4] = make_uint4(0, 0, 0, 0);
                }
            }
            __syncthreads();  // B

#pragma unroll
            for (int mi = 0; mi < 2; mi++) {
                int row = wm * 32 + mi * 16 + g;
                float s0 = S->sm_sc[row], s1 = S->sm_sc[row + 8];
#pragma unroll
                for (int ni = 0; ni < 4; ni++) {
                    acc[mi][ni][0] *= s0; acc[mi][ni][1] *= s0;
                    acc[mi][ni][2] *= s1; acc[mi][ni][3] *= s1;
                }
            }
#pragma unroll
            for (int kk = 0; kk < 64; kk += 8) {
                uint32_t af[2][4];
#pragma unroll
                for (int mi = 0; mi < 2; mi++) {
                    int mb = wm * 32 + mi * 16 + g;
                    af[mi][0] = S->Ps[mb][kk + tig];
                    af[mi][1] = S->Ps[mb + 8][kk + tig];
                    af[mi][2] = S->Ps[mb][kk + tig + 4];
                    af[mi][3] = S->Ps[mb + 8][kk + tig + 4];
                }
#pragma unroll
                for (int ni = 0; ni < 4; ni++) {
                    int nb = wn * 32 + ni * 8 + g;
                    uint32_t bf[2];
                    bf[0] = S->vhi[kk + tig][nb];
                    bf[1] = S->vhi[kk + tig + 4][nb];
#pragma unroll
                    for (int mi = 0; mi < 2; mi++) mma8(acc[mi][ni], af[mi], bf);
                }
            }
            __syncthreads();  // C
        }

        if (more) {
#pragma unroll
            for (int c = 0; c < 4; c++) {
                ks[c * 16 + ac4 + 0][ar] = kr[c].x;
                ks[c * 16 + ac4 + 1][ar] = kr[c].y;
                ks[c * 16 + ac4 + 2][ar] = kr[c].z;
                ks[c * 16 + ac4 + 3][ar] = kr[c].w;
            }
#pragma unroll
            for (int j = 0; j < 4; j++) {
                uint4 t;
                t.x = f2tf(vrg[j].x); t.y = f2tf(vrg[j].y);
                t.z = f2tf(vrg[j].z); t.w = f2tf(vrg[j].w);
                *(uint4*)&S->vhi[vr][vc + j * 4] = t;
            }
        }
        __syncthreads();  // D
    }
    {
        size_t obase = (size_t)b * EE * TT + (size_t)h * 64 * TT;
#pragma unroll
        for (int mi = 0; mi < 2; mi++) {
            int row = wm * 32 + mi * 16 + g;
            float i0 = 1.0f / S->sm_l[row];
            float i1 = 1.0f / S->sm_l[row + 8];
            int m = q0 + row;
#pragma unroll
            for (int ni = 0; ni < 4; ni++) {
                int n = wn * 32 + ni * 8 + tig * 2;
                g_athi[obase + (size_t)n * TT + m] = f2tf(acc[mi][ni][0] * i0);
                g_athi[obase + (size_t)(n + 1) * TT + m] = f2tf(acc[mi][ni][1] * i0);
                g_athi[obase + (size_t)n * TT + m + 8] = f2tf(acc[mi][ni][2] * i1);
                g_athi[obase + (size_t)(n + 1) * TT + m + 8] = f2tf(acc[mi][ni][3] * i1);
            }
        }
    }
}

// ---------------- LN finalize (from fused GEMM accumulators) -----------------
__global__ void ln_finalize2(int which) {
    int b = threadIdx.x;  // BB threads
    if (b >= BB) return;
    double n = (double)LN_N;
    double mean = g_lnacc[which][b][0] / n;
    double var = g_lnacc[which][b][1] / n - mean * mean;
    g_stats[b * 2] = (float)mean;
    g_stats[b * 2 + 1] = (float)(1.0 / sqrt(var + 1e-5));
}

// LN1 fused with transpose: writes z1 AND transposed tf32 athi
__global__ __launch_bounds__(256) void ln_norm_t(
    const float* __restrict__ in1, const float* __restrict__ in2,
    const float* __restrict__ w, const float* __restrict__ bia,
    float* __restrict__ out, uint32_t* __restrict__ ohi) {
    __shared__ float t[32][33];
    int m0 = blockIdx.y * 32, k0 = blockIdx.x * 32;
    int tx = threadIdx.x & 31, ty = threadIdx.x >> 5;
    int b = m0 / TT;
    float mean = g_stats[b * 2];
    float rstd = g_stats[b * 2 + 1];
#pragma unroll
    for (int i = ty; i < 32; i += 8) {
        int row = m0 + i;
        size_t idx = (size_t)row * EE + k0 + tx;
        size_t te = (size_t)(row % TT) * EE + k0 + tx;
        float v = (in1[idx] + in2[idx] - mean) * rstd * w[te] + bia[te];
        out[idx] = v;
        t[i][tx] = v;
    }
    __syncthreads();
#pragma unroll
    for (int i = ty; i < 32; i += 8) {
        ohi[(size_t)(k0 + i) * (BB * TT) + m0 + tx] = f2tf(t[tx][i]);
    }
}

// transpose + tf32 (x feed)
__global__ __launch_bounds__(256) void transpose_tf(
    const float* __restrict__ in, uint32_t* __restrict__ ohi, int M, int K) {
    __shared__ float t[32][33];
    int m0 = blockIdx.y * 32, k0 = blockIdx.x * 32;
    int tx = threadIdx.x & 31, ty = threadIdx.x >> 5;
#pragma unroll
    for (int i = ty; i < 32; i += 8) t[i][tx] = in[(size_t)(m0 + i) * K + k0 + tx];
    __syncthreads();
#pragma unroll
    for (int i = ty; i < 32; i += 8) {
        ohi[(size_t)(k0 + i) * M + m0 + tx] = f2tf(t[tx][i]);
    }
}

__global__ __launch_bounds__(256) void ln_norm(const float* __restrict__ in1,
                                               const float* __restrict__ in2,
                                               const float* __restrict__ w,
                                               const float* __restrict__ bia,
                                               float* __restrict__ out) {
    size_t i = ((size_t)blockIdx.x * blockDim.x + threadIdx.x) * 4;
    if (i >= (size_t)BB * LN_N) return;
    int b = (int)(i / LN_N);
    size_t te = i % LN_N;
    float mean = g_stats[b * 2];
    float rstd = g_stats[b * 2 + 1];
    float4 a = *(const float4*)&in1[i];
    float4 c = *(const float4*)&in2[i];
    float4 ww = *(const float4*)&w[te];
    float4 bb = *(const float4*)&bia[te];
    float4 o;
    o.x = (a.x + c.x - mean) * rstd * ww.x + bb.x;
    o.y = (a.y + c.y - mean) * rstd * ww.y + bb.y;
    o.z = (a.z + c.z - mean) * rstd * ww.z + bb.z;
    o.w = (a.w + c.w - mean) * rstd * ww.w + bb.w;
    *(float4*)&out[i] = o;
}

// ---------------- launch -----------------------------------------------------
extern "C" void kernel_launch(void* const* d_in, const int* in_sizes, int n_in,
                              void* d_out, int out_size) {
    const float* x = (const float*)d_in[0];
    const float* q_w = (const float*)d_in[1];
    const float* k_w = (const float*)d_in[2];
    const float* v_w = (const float*)d_in[3];
    const float* fr_w = (const float*)d_in[4];
    const float* ff_w = (const float*)d_in[5];
    const float* ff_b = (const float*)d_in[6];
    const float* ln1_w = (const float*)d_in[7];
    const float* ln1_b = (const float*)d_in[8];
    const float* ln2_w = (const float*)d_in[9];
    const float* ln2_b = (const float*)d_in[10];
    float* out = (float*)d_out;

    float *p_wq, *p_wk, *p_q, *p_k, *p_v, *p_zf, *p_z1, *p_z2;
    uint32_t *p_wvhi, *p_wffhi, *p_frhi, *p_athi;
    cudaGetSymbolAddress((void**)&p_wq, g_wq);
    cudaGetSymbolAddress((void**)&p_wk, g_wk);
    cudaGetSymbolAddress((void**)&p_q, g_q);
    cudaGetSymbolAddress((void**)&p_k, g_k);
    cudaGetSymbolAddress((void**)&p_v, g_v);
    cudaGetSymbolAddress((void**)&p_zf, g_zf);
    cudaGetSymbolAddress((void**)&p_z1, g_z1);
    cudaGetSymbolAddress((void**)&p_z2, g_z2);
    cudaGetSymbolAddress((void**)&p_wvhi, g_wvhi);
    cudaGetSymbolAddress((void**)&p_wffhi, g_wffhi);
    cudaGetSymbolAddress((void**)&p_frhi, g_frhi);
    cudaGetSymbolAddress((void**)&p_athi, g_athi);

    const size_t SMP = 3 * T1_STAGE_U32 * sizeof(uint32_t);
    const size_t SMA = sizeof(AttnSmem);
    cudaFuncSetAttribute(attn_fused, cudaFuncAttributeMaxDynamicSharedMemorySize, (int)SMA);
    cudaFuncSetAttribute(gemm_qkv, cudaFuncAttributeMaxDynamicSharedMemorySize, (int)SMP);
    cudaFuncSetAttribute(gemm_tf1<false>, cudaFuncAttributeMaxDynamicSharedMemorySize, (int)SMP);
    cudaFuncSetAttribute(gemm_tf1<true>, cudaFuncAttributeMaxDynamicSharedMemorySize, (int)SMP);

    // 1) merged weight repacks + accumulator resets
    int repack_total = EE * EE + BB * EE * EE;
    repack_all<<<(repack_total + 255) / 256, 256>>>(q_w, k_w, v_w, ff_w, fr_w);

    // 2) transpose x (feeds V path of merged kernel)
    dim3 gtx(EE / 32, (BB * TT) / 32, 1);
    transpose_tf<<<gtx, 256>>>(x, p_athi, BB * TT, EE);

    // 3) merged QKV (Q/K epilogues also emit norm maxima for the skip bound)
    dim3 gqkv(EE / 128, (BB * TT) / 128, 3);
    gemm_qkv<<<gqkv, 256, SMP>>>(x, p_wq, p_wk, p_q, p_k,
                                 p_athi, p_wvhi, p_v, BB * TT, EE, EE);

    // 4) fused attention (descending k, provable early break)
    dim3 gat(TT / 128, BB * HH, 1);
    attn_fused<<<gat, 256, SMA>>>();

    // 5) zf[b] = zm[b] @ fr[b]  (+ fused LN1 reduction over x + zf)
    dim3 gfr(EE / 128, TT / 128, BB);
    gemm_tf1<false><<<gfr, 256, SMP>>>(p_athi, p_frhi, p_zf,
                                       TT, EE, EE, (long)TT * EE, (long)EE * EE,
                                       (long)TT * EE, nullptr, x, 0);

    // 6) LN1 finalize + normalize (fused with transpose to athi)
    ln_finalize2<<<1, BB>>>(0);
    ln_norm_t<<<gtx, 256>>>(x, p_zf, ln1_w, ln1_b, p_z1, p_athi);

    // 7) FFN: z2 = relu(z1 @ ff_w^T + ff_b)  (+ fused LN2 reduction over z1+z2)
    dim3 gv(EE / 128, (BB * TT) / 128, 1);
    gemm_tf1<true><<<gv, 256, SMP>>>(p_athi, p_wffhi, p_z2,
                                     BB * TT, EE, EE, 0, 0, 0, ff_b, p_z1, 1);

    // 8) LN2 finalize + normalize -> out
    ln_finalize2<<<1, BB>>>(1);
    size_t total = (size_t)BB * LN_N;
    ln_norm<<<(unsigned)((total / 4 + 255) / 256), 256>>>(p_z1, p_z2, ln2_w, ln2_b, out);
}